// round 11
// baseline (speedup 1.0000x reference)
#include <cuda_runtime.h>
#include <cuda_fp16.h>
#include <math.h>
#include <stdint.h>

#define D_MODEL   2048
#define D_INNER   4096
#define D_STATE   128
#define HEADDIM   64
#define NHEADS    64
#define CONV_DIM  4352     /* D_INNER + 2*D_STATE */
#define D_IN_PROJ 8512     /* 2*D_INNER + 2*D_STATE + NHEADS */
#define BATCH     2
#define TLEN      2048
#define NTOK      (BATCH*TLEN)   /* 4096 */
#define RMS_EPS   1e-5f

#define SSEG 16
#define TSEG (TLEN / SSEG)       /* 128 */
#define HSTATE (HEADDIM * D_STATE)  /* 8192 */

// ---------------- scratch (device globals; no allocs allowed) ----------------
__device__ float g_zx [(size_t)NTOK * D_IN_PROJ];
__device__ float g_xbc[(size_t)NTOK * CONV_DIM];
__device__ float g_y  [(size_t)NTOK * D_INNER];
__device__ float g_hseg[(size_t)BATCH * NHEADS * SSEG * HSTATE];
__device__ float g_sumdt[BATCH * NHEADS * SSEG];

__device__ __half g_xc [(size_t)NTOK * D_MODEL];
__device__ __half g_w1c[(size_t)2 * D_IN_PROJ * D_MODEL];
__device__ __half g_yc [(size_t)NTOK * D_INNER];
__device__ __half g_w2c[(size_t)2 * D_MODEL * D_INNER];

__device__ __forceinline__ uint32_t smem_to_u32(const void* p) {
    uint32_t a;
    asm("{ .reg .u64 t; cvta.to.shared.u64 t, %1; cvt.u32.u64 %0, t; }" : "=r"(a) : "l"(p));
    return a;
}

// ---------------- packed f32x2 helpers (Blackwell plain PTX, sm_100+) ----------------
__device__ __forceinline__ unsigned long long bcast2(float v) {
    unsigned long long r;
    const uint32_t u = __float_as_uint(v);
    asm("mov.b64 %0, {%1, %1};" : "=l"(r) : "r"(u));
    return r;
}
__device__ __forceinline__ unsigned long long mul2(unsigned long long a, unsigned long long b) {
    unsigned long long d;
    asm("mul.rn.f32x2 %0, %1, %2;" : "=l"(d) : "l"(a), "l"(b));
    return d;
}
__device__ __forceinline__ unsigned long long fma2(unsigned long long a, unsigned long long b,
                                                   unsigned long long c) {
    unsigned long long d;
    asm("fma.rn.f32x2 %0, %1, %2, %3;" : "=l"(d) : "l"(a), "l"(b), "l"(c));
    return d;
}
__device__ __forceinline__ float hsum2(unsigned long long v) {
    uint32_t lo, hi;
    asm("mov.b64 {%0, %1}, %2;" : "=r"(lo), "=r"(hi) : "l"(v));
    return __uint_as_float(lo) + __uint_as_float(hi);
}

// ---------------- fp32 -> fp16 hi plane only ----------------
__global__ void __launch_bounds__(256) cvt_hi_kernel(
    const float* __restrict__ src, __half* __restrict__ hi, int n4)
{
    const int i = blockIdx.x * 256 + threadIdx.x;
    if (i >= n4) return;
    const float4 v = ((const float4*)src)[i];
    __half2* hp = (__half2*)(hi + (size_t)i * 4);
    hp[0] = __halves2half2(__float2half_rn(v.x), __float2half_rn(v.y));
    hp[1] = __halves2half2(__float2half_rn(v.z), __float2half_rn(v.w));
}

// ---------------- fp32 -> (hi, lo) fp16 planes (weights) ----------------
__global__ void __launch_bounds__(256) cvt_f16x2_kernel(
    const float* __restrict__ src, __half* __restrict__ hi, __half* __restrict__ lo, int n4)
{
    const int i = blockIdx.x * 256 + threadIdx.x;
    if (i >= n4) return;
    const float4 v = ((const float4*)src)[i];
    __half h0 = __float2half_rn(v.x), h1 = __float2half_rn(v.y);
    __half h2 = __float2half_rn(v.z), h3 = __float2half_rn(v.w);
    __half l0 = __float2half_rn(v.x - __half2float(h0));
    __half l1 = __float2half_rn(v.y - __half2float(h1));
    __half l2 = __float2half_rn(v.z - __half2float(h2));
    __half l3 = __float2half_rn(v.w - __half2float(h3));
    __half2* hp = (__half2*)(hi + (size_t)i * 4);
    __half2* lp = (__half2*)(lo + (size_t)i * 4);
    hp[0] = __halves2half2(h0, h1); hp[1] = __halves2half2(h2, h3);
    lp[0] = __halves2half2(l0, l1); lp[1] = __halves2half2(l2, l3);
}

// ======== fp16x2 GEMM: 128x128 tile, 3-stage pipeline, 2 CTAs/SM ========
#define PADH 40
#define PLANE_H (128 * PADH)
#define STAGE_B (3 * PLANE_H * 2)          /* Ahi Bhi Blo = 30720 bytes */
#define GEMM_SMEM (3 * STAGE_B)            /* 92160 B; x2 CTAs <= 228KB */

__device__ __forceinline__ void mma16816(float* c, const uint32_t* a, const uint32_t* b) {
    asm volatile(
        "mma.sync.aligned.m16n8k16.row.col.f32.f16.f16.f32 "
        "{%0,%1,%2,%3}, {%4,%5,%6,%7}, {%8,%9}, {%0,%1,%2,%3};"
        : "+f"(c[0]), "+f"(c[1]), "+f"(c[2]), "+f"(c[3])
        : "r"(a[0]), "r"(a[1]), "r"(a[2]), "r"(a[3]), "r"(b[0]), "r"(b[1]));
}
__device__ __forceinline__ void ldsm4(uint32_t& r0, uint32_t& r1, uint32_t& r2, uint32_t& r3,
                                      uint32_t addr) {
    asm volatile("ldmatrix.sync.aligned.m8n8.x4.shared.b16 {%0,%1,%2,%3}, [%4];"
                 : "=r"(r0), "=r"(r1), "=r"(r2), "=r"(r3) : "r"(addr));
}

__global__ void __launch_bounds__(256, 2) mma_gemm_f16x2(
    const __half* __restrict__ Ahi,
    const __half* __restrict__ Bhi, const __half* __restrict__ Blo,
    float* __restrict__ C, int M, int N, int K)
{
    extern __shared__ __half sh[];
    const int tid  = threadIdx.x;
    const int wid  = tid >> 5;
    const int lane = tid & 31;
    const int g    = lane >> 2;
    const int tig  = lane & 3;
    const int bm   = blockIdx.x * 128;
    const int bn   = blockIdx.y * 128;
    const int wm   = (wid & 1) * 64;
    const int wn   = (wid >> 1) * 32;

    const uint32_t sbase = smem_to_u32(sh);

    const int a_r = lane & 15;
    const int a_c = (lane >> 4) * 8;
    const int b_r = (lane & 7) + ((lane >> 4) << 3);
    const int b_c = ((lane >> 3) & 1) * 8;

    float acc[4][4][4];
#pragma unroll
    for (int mt = 0; mt < 4; ++mt)
#pragma unroll
        for (int nt = 0; nt < 4; ++nt)
#pragma unroll
            for (int q = 0; q < 4; ++q) acc[mt][nt][q] = 0.f;

    const int NC = K >> 5;

    auto load_stage = [&](int s, int c) {
        const int kb = c * 32;
        const uint32_t stg = sbase + (uint32_t)s * STAGE_B;
#pragma unroll
        for (int i = 0; i < 2; ++i) {
            const int f   = tid + 256 * i;
            const int row = f >> 2;
            const int seg = (f & 3) * 8;
            const uint32_t doff = (uint32_t)(row * PADH + seg) * 2u;
            {
                const __half* p = Ahi + (size_t)(bm + row) * K + kb + seg;
                asm volatile("cp.async.cg.shared.global [%0], [%1], 16;"
                             :: "r"(stg + doff), "l"(p) : "memory");
            }
            {
                const int brow = bn + row;
                const int safe = (brow < N) ? brow : 0;
                const uint32_t sz = (brow < N) ? 16u : 0u;
                const __half* p  = Bhi + (size_t)safe * K + kb + seg;
                asm volatile("cp.async.cg.shared.global [%0], [%1], 16, %2;"
                             :: "r"(stg + (uint32_t)PLANE_H * 2u + doff), "l"(p), "r"(sz) : "memory");
                const __half* q2 = Blo + (size_t)safe * K + kb + seg;
                asm volatile("cp.async.cg.shared.global [%0], [%1], 16, %2;"
                             :: "r"(stg + (uint32_t)(2 * PLANE_H) * 2u + doff), "l"(q2), "r"(sz) : "memory");
            }
        }
        asm volatile("cp.async.commit_group;" ::: "memory");
    };

    auto compute_stage = [&](int s) {
        const uint32_t stg = sbase + (uint32_t)s * STAGE_B;
        const uint32_t aHi = stg;
        const uint32_t bHi = stg + (uint32_t)PLANE_H * 2u;
        const uint32_t bLo = stg + (uint32_t)(2 * PLANE_H) * 2u;
#pragma unroll
        for (int ks = 0; ks < 2; ++ks) {
            const int k0 = ks * 16;
            uint32_t ah[4][4], bh[4][2], bl[4][2];
#pragma unroll
            for (int p = 0; p < 2; ++p) {
                const uint32_t off = (uint32_t)((wn + p * 16 + b_r) * PADH + k0 + b_c) * 2u;
                ldsm4(bh[2*p][0], bh[2*p][1], bh[2*p+1][0], bh[2*p+1][1], bHi + off);
                ldsm4(bl[2*p][0], bl[2*p][1], bl[2*p+1][0], bl[2*p+1][1], bLo + off);
            }
#pragma unroll
            for (int mt = 0; mt < 4; ++mt) {
                const uint32_t off = (uint32_t)((wm + mt * 16 + a_r) * PADH + k0 + a_c) * 2u;
                ldsm4(ah[mt][0], ah[mt][1], ah[mt][2], ah[mt][3], aHi + off);
            }
#pragma unroll
            for (int mt = 0; mt < 4; ++mt)
#pragma unroll
                for (int nt = 0; nt < 4; ++nt)
                    mma16816(acc[mt][nt], ah[mt], bh[nt]);
#pragma unroll
            for (int mt = 0; mt < 4; ++mt)
#pragma unroll
                for (int nt = 0; nt < 4; ++nt)
                    mma16816(acc[mt][nt], ah[mt], bl[nt]);
        }
    };

    load_stage(0, 0);
    load_stage(1, 1);
    for (int c = 0; c < NC; ++c) {
        if (c + 2 < NC) {
            asm volatile("cp.async.wait_group 1;" ::: "memory");
        } else {
            asm volatile("cp.async.wait_group 0;" ::: "memory");
        }
        __syncthreads();
        if (c + 2 < NC) load_stage((c + 2) % 3, c + 2);
        compute_stage(c % 3);
    }

#pragma unroll
    for (int mt = 0; mt < 4; ++mt) {
        const int row0 = bm + wm + mt * 16 + g;
#pragma unroll
        for (int nt = 0; nt < 4; ++nt) {
            const int col = bn + wn + nt * 8 + tig * 2;
            if (col < N) {
                *(float2*)(C + (size_t)row0 * N + col)       = make_float2(acc[mt][nt][0], acc[mt][nt][1]);
                *(float2*)(C + (size_t)(row0 + 8) * N + col) = make_float2(acc[mt][nt][2], acc[mt][nt][3]);
            }
        }
    }
}

// ---------------- depthwise causal conv (width 4) + SiLU ----------------
__global__ void __launch_bounds__(256) conv_silu_kernel(
    const float* __restrict__ cw, const float* __restrict__ cb)
{
    const int c  = blockIdx.x * 256 + threadIdx.x;
    const int b  = blockIdx.z;
    const int t0 = blockIdx.y * 32;

    const float w0 = cw[c*4+0], w1 = cw[c*4+1], w2 = cw[c*4+2], w3 = cw[c*4+3];
    const float bias = cb[c];

    const float* base = g_zx + ((size_t)b * TLEN) * D_IN_PROJ + D_INNER + c;
    float* ob = g_xbc + ((size_t)b * TLEN) * CONV_DIM + c;

    float x0 = (t0 >= 3) ? base[(size_t)(t0-3) * D_IN_PROJ] : 0.f;
    float x1 = (t0 >= 2) ? base[(size_t)(t0-2) * D_IN_PROJ] : 0.f;
    float x2 = (t0 >= 1) ? base[(size_t)(t0-1) * D_IN_PROJ] : 0.f;

    for (int t = t0; t < t0 + 32; ++t) {
        const float x3 = base[(size_t)t * D_IN_PROJ];
        const float v  = bias + x0*w0 + x1*w1 + x2*w2 + x3*w3;
        ob[(size_t)t * CONV_DIM] = v / (1.f + expf(-v));
        x0 = x1; x1 = x2; x2 = x3;
    }
}

// ---------------- segmented SSM scan: pass A (local scans, f32x2 packed) ----------------
#define SCAN_TC 8
__global__ void __launch_bounds__(128) scan_seg_kernel(
    const float* __restrict__ dt_bias, const float* __restrict__ A_log,
    const float* __restrict__ Dskip)
{
    const int h   = blockIdx.x;
    const int b   = blockIdx.y;
    const int s   = blockIdx.z;
    const int tid = threadIdx.x;
    const int p    = tid >> 1;
    const int half = tid & 1;
    const int nb   = half * 64;

    __shared__ __align__(16) float sB[SCAN_TC][128];
    __shared__ __align__(16) float sC[SCAN_TC][128];
    __shared__ __align__(16) float sX[SCAN_TC][64];
    __shared__ float sDA[SCAN_TC], sDT[SCAN_TC];
    __shared__ float sred[8];

    unsigned long long h2[32];
#pragma unroll
    for (int q = 0; q < 32; ++q) h2[q] = 0ull;

    const float Acoef = -expf(A_log[h]);
    const float dtb   = dt_bias[h];
    const float dsk   = Dskip[h];

    const float* xbc_b    = g_xbc + (size_t)b * TLEN * CONV_DIM;
    const float* dtr_base = g_zx  + (size_t)b * TLEN * D_IN_PROJ + (D_INNER + CONV_DIM) + h;
    float*       y_base   = g_y   + (size_t)b * TLEN * D_INNER + h * HEADDIM;

    const int tbeg = s * TSEG;
    float sumdt_part = 0.f;

    for (int t0 = tbeg; t0 < tbeg + TSEG; t0 += SCAN_TC) {
#pragma unroll
        for (int tl = 0; tl < SCAN_TC; ++tl) {
            const float* row = xbc_b + (size_t)(t0 + tl) * CONV_DIM;
            sB[tl][tid] = row[D_INNER + tid];
            sC[tl][tid] = row[D_INNER + D_STATE + tid];
            if (tid < 64) sX[tl][tid] = row[h * HEADDIM + tid];
        }
        if (tid < SCAN_TC) {
            const float raw = dtr_base[(size_t)(t0 + tid) * D_IN_PROJ] + dtb;
            const float dt  = (raw > 20.f) ? raw : log1pf(expf(raw));
            sDT[tid] = dt;
            sDA[tid] = expf(dt * Acoef);
            sumdt_part += dt;
        }
        __syncthreads();

#pragma unroll
        for (int tl = 0; tl < SCAN_TC; ++tl) {
            const unsigned long long dA2  = bcast2(sDA[tl]);
            const unsigned long long dtx2 = bcast2(sDT[tl] * sX[tl][p]);
            const ulonglong2* B2 = (const ulonglong2*)&sB[tl][nb];
            const ulonglong2* C2 = (const ulonglong2*)&sC[tl][nb];
            unsigned long long ya = 0ull, yb = 0ull;
#pragma unroll
            for (int q = 0; q < 16; ++q) {
                const ulonglong2 bb = B2[q];
                const ulonglong2 cc = C2[q];
                h2[2*q]   = fma2(h2[2*q],   dA2, mul2(dtx2, bb.x));
                ya = fma2(h2[2*q],   cc.x, ya);
                h2[2*q+1] = fma2(h2[2*q+1], dA2, mul2(dtx2, bb.y));
                yb = fma2(h2[2*q+1], cc.y, yb);
            }
            float y = hsum2(ya) + hsum2(yb);
            y += __shfl_xor_sync(0xffffffffu, y, 1);
            if (half == 0) {
                y += dsk * sX[tl][p];
                y_base[(size_t)(t0 + tl) * D_INNER + p] = y;
            }
        }
        __syncthreads();
    }

    // write local end state (same float layout as before)
    ulonglong2* dst = (ulonglong2*)(g_hseg + ((size_t)((b * NHEADS + h) * SSEG + s)) * HSTATE
                                    + p * D_STATE + nb);
#pragma unroll
    for (int q = 0; q < 16; ++q) {
        ulonglong2 v; v.x = h2[2*q]; v.y = h2[2*q+1];
        dst[q] = v;
    }

    if (tid < 8) sred[tid] = sumdt_part;
    __syncthreads();
    if (tid == 0) {
        float t = 0.f;
#pragma unroll
        for (int i = 0; i < 8; ++i) t += sred[i];
        g_sumdt[(b * NHEADS + h) * SSEG + s] = t;
    }
}

// ---------------- pass B: sequential combine of segment boundary states ----------------
__global__ void __launch_bounds__(256) seg_combine_kernel(const float* __restrict__ A_log)
{
    const int bh  = blockIdx.x;
    const int h   = bh & (NHEADS - 1);
    const int tid = threadIdx.x;
    const float Acoef = -expf(A_log[h]);

    float4 carry[8];
#pragma unroll
    for (int i = 0; i < 8; ++i) carry[i] = make_float4(0.f,0.f,0.f,0.f);

    float* base = g_hseg + (size_t)bh * SSEG * HSTATE + tid * 32;
#pragma unroll
    for (int s = 0; s < SSEG; ++s) {
        const float P = expf(Acoef * g_sumdt[bh * SSEG + s]);
        float4* slot = (float4*)(base + (size_t)s * HSTATE);
#pragma unroll
        for (int i = 0; i < 8; ++i) {
            const float4 hend = slot[i];
            const float4 old  = carry[i];
            slot[i] = old;
            carry[i].x = P * old.x + hend.x;
            carry[i].y = P * old.y + hend.y;
            carry[i].z = P * old.z + hend.z;
            carry[i].w = P * old.w + hend.w;
        }
    }
}

// ---------------- pass C: correction y_t += prefix_t * (C_t . Hstart), f32x2 ----------------
__global__ void __launch_bounds__(128) seg_correct_kernel(
    const float* __restrict__ dt_bias, const float* __restrict__ A_log)
{
    const int h   = blockIdx.x;
    const int b   = blockIdx.y;
    const int s   = blockIdx.z + 1;
    const int tid = threadIdx.x;
    const int p    = tid >> 1;
    const int half = tid & 1;
    const int nb   = half * 64;

    __shared__ __align__(16) float sC[SCAN_TC][128];
    __shared__ float sDA[SCAN_TC];

    unsigned long long hs2[32];
    const ulonglong2* src = (const ulonglong2*)(g_hseg
                            + ((size_t)((b * NHEADS + h) * SSEG + s)) * HSTATE
                            + p * D_STATE + nb);
#pragma unroll
    for (int q = 0; q < 16; ++q) {
        const ulonglong2 v = src[q];
        hs2[2*q] = v.x; hs2[2*q+1] = v.y;
    }

    const float Acoef = -expf(A_log[h]);
    const float dtb   = dt_bias[h];

    const float* xbc_b    = g_xbc + (size_t)b * TLEN * CONV_DIM;
    const float* dtr_base = g_zx  + (size_t)b * TLEN * D_IN_PROJ + (D_INNER + CONV_DIM) + h;
    float*       y_base   = g_y   + (size_t)b * TLEN * D_INNER + h * HEADDIM;

    float carryP = 1.f;
    const int tbeg = s * TSEG;

    for (int t0 = tbeg; t0 < tbeg + TSEG; t0 += SCAN_TC) {
#pragma unroll
        for (int tl = 0; tl < SCAN_TC; ++tl) {
            const float* row = xbc_b + (size_t)(t0 + tl) * CONV_DIM;
            sC[tl][tid] = row[D_INNER + D_STATE + tid];
        }
        if (tid < SCAN_TC) {
            const float raw = dtr_base[(size_t)(t0 + tid) * D_IN_PROJ] + dtb;
            const float dt  = (raw > 20.f) ? raw : log1pf(expf(raw));
            sDA[tid] = expf(dt * Acoef);
        }
        __syncthreads();

        float pref = carryP;
#pragma unroll
        for (int tl = 0; tl < SCAN_TC; ++tl) {
            pref *= sDA[tl];
            const ulonglong2* C2 = (const ulonglong2*)&sC[tl][nb];
            unsigned long long da = 0ull, db = 0ull;
#pragma unroll
            for (int q = 0; q < 16; ++q) {
                const ulonglong2 cc = C2[q];
                da = fma2(hs2[2*q],   cc.x, da);
                db = fma2(hs2[2*q+1], cc.y, db);
            }
            float dot = hsum2(da) + hsum2(db);
            dot += __shfl_xor_sync(0xffffffffu, dot, 1);
            if (half == 0)
                y_base[(size_t)(t0 + tl) * D_INNER + p] += pref * dot;
        }
        carryP = pref;
        __syncthreads();
    }
}

// ---------------- gate + RMSNorm, emits fp16 hi plane directly ----------------
__global__ void __launch_bounds__(256) gate_norm_cvt_kernel(
    const float* __restrict__ nw, __half* __restrict__ yhi)
{
    const int row = blockIdx.x;
    const int tid = threadIdx.x;
    const float* zrow = g_zx + (size_t)row * D_IN_PROJ;
    const float* yrow = g_y  + (size_t)row * D_INNER;

    float g[16];
    float ss = 0.f;
#pragma unroll
    for (int i = 0; i < 4; ++i) {
        const int e = i * 1024 + tid * 4;
        const float4 yv = *(const float4*)(yrow + e);
        const float4 zv = *(const float4*)(zrow + e);
        float g0 = yv.x * (zv.x / (1.f + expf(-zv.x)));
        float g1 = yv.y * (zv.y / (1.f + expf(-zv.y)));
        float g2 = yv.z * (zv.z / (1.f + expf(-zv.z)));
        float g3 = yv.w * (zv.w / (1.f + expf(-zv.w)));
        g[i*4+0] = g0; g[i*4+1] = g1; g[i*4+2] = g2; g[i*4+3] = g3;
        ss += g0*g0 + g1*g1 + g2*g2 + g3*g3;
    }

    ss += __shfl_xor_sync(0xffffffffu, ss, 16);
    ss += __shfl_xor_sync(0xffffffffu, ss, 8);
    ss += __shfl_xor_sync(0xffffffffu, ss, 4);
    ss += __shfl_xor_sync(0xffffffffu, ss, 2);
    ss += __shfl_xor_sync(0xffffffffu, ss, 1);
    __shared__ float red[8];
    if ((tid & 31) == 0) red[tid >> 5] = ss;
    __syncthreads();
    float tot = 0.f;
#pragma unroll
    for (int w = 0; w < 8; ++w) tot += red[w];

    const float scale = rsqrtf(tot / (float)D_INNER + RMS_EPS);
#pragma unroll
    for (int i = 0; i < 4; ++i) {
        const int e = i * 1024 + tid * 4;
        const float v0 = g[i*4+0] * scale * nw[e+0];
        const float v1 = g[i*4+1] * scale * nw[e+1];
        const float v2 = g[i*4+2] * scale * nw[e+2];
        const float v3 = g[i*4+3] * scale * nw[e+3];
        __half2* hp = (__half2*)(yhi + (size_t)row * D_INNER + e);
        hp[0] = __halves2half2(__float2half_rn(v0), __float2half_rn(v1));
        hp[1] = __halves2half2(__float2half_rn(v2), __float2half_rn(v3));
    }
}

// ---------------- launch ----------------
extern "C" void kernel_launch(void* const* d_in, const int* in_sizes, int n_in,
                              void* d_out, int out_size)
{
    const float* x          = (const float*)d_in[0];
    const float* in_proj_w  = (const float*)d_in[3];
    const float* conv_w     = (const float*)d_in[4];
    const float* conv_b     = (const float*)d_in[5];
    const float* dt_bias    = (const float*)d_in[6];
    const float* A_log      = (const float*)d_in[7];
    const float* Dskip      = (const float*)d_in[8];
    const float* norm_w     = (const float*)d_in[9];
    const float* out_proj_w = (const float*)d_in[10];
    float* out = (float*)d_out;

    float *zx;
    __half *xc, *w1c, *yc, *w2c;
    cudaGetSymbolAddress((void**)&zx,  g_zx);
    cudaGetSymbolAddress((void**)&xc,  g_xc);
    cudaGetSymbolAddress((void**)&w1c, g_w1c);
    cudaGetSymbolAddress((void**)&yc,  g_yc);
    cudaGetSymbolAddress((void**)&w2c, g_w2c);

    cudaFuncSetAttribute(mma_gemm_f16x2,
                         cudaFuncAttributeMaxDynamicSharedMemorySize, GEMM_SMEM);

    // 0) convert: x -> hi plane; weights -> hi+lo planes
    {
        const int nx = NTOK * D_MODEL / 4;
        cvt_hi_kernel<<<(nx + 255) / 256, 256>>>(x, xc, nx);
        const int nw1 = D_IN_PROJ * D_MODEL / 4;
        cvt_f16x2_kernel<<<(nw1 + 255) / 256, 256>>>(in_proj_w, w1c, w1c + (size_t)D_IN_PROJ * D_MODEL, nw1);
        const int nw2 = D_MODEL * D_INNER / 4;
        cvt_f16x2_kernel<<<(nw2 + 255) / 256, 256>>>(out_proj_w, w2c, w2c + (size_t)D_MODEL * D_INNER, nw2);
    }

    // 1) in_proj: zx[4096, 8512] = x * W1^T
    {
        dim3 grid(NTOK / 128, (D_IN_PROJ + 127) / 128);
        mma_gemm_f16x2<<<grid, 256, GEMM_SMEM>>>(
            xc, w1c, w1c + (size_t)D_IN_PROJ * D_MODEL,
            zx, NTOK, D_IN_PROJ, D_MODEL);
    }
    // 2) conv + silu
    {
        dim3 grid(CONV_DIM / 256, TLEN / 32, BATCH);
        conv_silu_kernel<<<grid, 256>>>(conv_w, conv_b);
    }
    // 3) segmented SSM scan: local scans -> combine -> correct
    {
        dim3 gridA(NHEADS, BATCH, SSEG);
        scan_seg_kernel<<<gridA, 128>>>(dt_bias, A_log, Dskip);
        seg_combine_kernel<<<BATCH * NHEADS, 256>>>(A_log);
        dim3 gridC(NHEADS, BATCH, SSEG - 1);
        seg_correct_kernel<<<gridC, 128>>>(dt_bias, A_log);
    }
    // 4) gate + RMSNorm + fp16 hi (fused)
    gate_norm_cvt_kernel<<<NTOK, 256>>>(norm_w, yc);

    // 5) out_proj: out[4096, 2048] = y * W2^T
    {
        dim3 grid(NTOK / 128, D_MODEL / 128);
        mma_gemm_f16x2<<<grid, 256, GEMM_SMEM>>>(
            yc, w2c, w2c + (size_t)D_MODEL * D_INNER,
            out, NTOK, D_MODEL, D_INNER);
    }
}

// round 12
// speedup vs baseline: 1.0734x; 1.0734x over previous
#include <cuda_runtime.h>
#include <cuda_fp16.h>
#include <math.h>
#include <stdint.h>

#define D_MODEL   2048
#define D_INNER   4096
#define D_STATE   128
#define HEADDIM   64
#define NHEADS    64
#define CONV_DIM  4352     /* D_INNER + 2*D_STATE */
#define D_IN_PROJ 8512     /* 2*D_INNER + 2*D_STATE + NHEADS */
#define BATCH     2
#define TLEN      2048
#define NTOK      (BATCH*TLEN)   /* 4096 */
#define RMS_EPS   1e-5f

#define SSEG 16
#define TSEG (TLEN / SSEG)       /* 128 */
#define HSTATE (HEADDIM * D_STATE)  /* 8192 */

// ---------------- scratch (device globals; no allocs allowed) ----------------
__device__ float g_zx [(size_t)NTOK * D_IN_PROJ];
__device__ float g_xbc[(size_t)NTOK * CONV_DIM];
__device__ float g_y  [(size_t)NTOK * D_INNER];
__device__ float g_hseg[(size_t)BATCH * NHEADS * SSEG * HSTATE];
__device__ float g_sumdt[BATCH * NHEADS * SSEG];

__device__ __half g_xc [(size_t)NTOK * D_MODEL];
__device__ __half g_w1c[(size_t)2 * D_IN_PROJ * D_MODEL];
__device__ __half g_yc [(size_t)NTOK * D_INNER];
__device__ __half g_w2c[(size_t)2 * D_MODEL * D_INNER];

__device__ __forceinline__ uint32_t smem_to_u32(const void* p) {
    uint32_t a;
    asm("{ .reg .u64 t; cvta.to.shared.u64 t, %1; cvt.u32.u64 %0, t; }" : "=r"(a) : "l"(p));
    return a;
}
__device__ __forceinline__ void cp16(uint32_t dst, const void* src) {
    asm volatile("cp.async.cg.shared.global [%0], [%1], 16;" :: "r"(dst), "l"(src) : "memory");
}

// ---------------- fp32 -> fp16 hi plane only ----------------
__global__ void __launch_bounds__(256) cvt_hi_kernel(
    const float* __restrict__ src, __half* __restrict__ hi, int n4)
{
    const int i = blockIdx.x * 256 + threadIdx.x;
    if (i >= n4) return;
    const float4 v = ((const float4*)src)[i];
    __half2* hp = (__half2*)(hi + (size_t)i * 4);
    hp[0] = __halves2half2(__float2half_rn(v.x), __float2half_rn(v.y));
    hp[1] = __halves2half2(__float2half_rn(v.z), __float2half_rn(v.w));
}

// ---------------- fp32 -> (hi, lo) fp16 planes (weights) ----------------
__global__ void __launch_bounds__(256) cvt_f16x2_kernel(
    const float* __restrict__ src, __half* __restrict__ hi, __half* __restrict__ lo, int n4)
{
    const int i = blockIdx.x * 256 + threadIdx.x;
    if (i >= n4) return;
    const float4 v = ((const float4*)src)[i];
    __half h0 = __float2half_rn(v.x), h1 = __float2half_rn(v.y);
    __half h2 = __float2half_rn(v.z), h3 = __float2half_rn(v.w);
    __half l0 = __float2half_rn(v.x - __half2float(h0));
    __half l1 = __float2half_rn(v.y - __half2float(h1));
    __half l2 = __float2half_rn(v.z - __half2float(h2));
    __half l3 = __float2half_rn(v.w - __half2float(h3));
    __half2* hp = (__half2*)(hi + (size_t)i * 4);
    __half2* lp = (__half2*)(lo + (size_t)i * 4);
    hp[0] = __halves2half2(h0, h1); hp[1] = __halves2half2(h2, h3);
    lp[0] = __halves2half2(l0, l1); lp[1] = __halves2half2(l2, l3);
}

// ======== fp16x2 GEMM: 128x128 tile, 3-stage pipeline, 2 CTAs/SM ========
#define PADH 40
#define PLANE_H (128 * PADH)
#define STAGE_B (3 * PLANE_H * 2)          /* Ahi Bhi Blo = 30720 bytes */
#define GEMM_SMEM (3 * STAGE_B)

__device__ __forceinline__ void mma16816(float* c, const uint32_t* a, const uint32_t* b) {
    asm volatile(
        "mma.sync.aligned.m16n8k16.row.col.f32.f16.f16.f32 "
        "{%0,%1,%2,%3}, {%4,%5,%6,%7}, {%8,%9}, {%0,%1,%2,%3};"
        : "+f"(c[0]), "+f"(c[1]), "+f"(c[2]), "+f"(c[3])
        : "r"(a[0]), "r"(a[1]), "r"(a[2]), "r"(a[3]), "r"(b[0]), "r"(b[1]));
}
__device__ __forceinline__ void ldsm4(uint32_t& r0, uint32_t& r1, uint32_t& r2, uint32_t& r3,
                                      uint32_t addr) {
    asm volatile("ldmatrix.sync.aligned.m8n8.x4.shared.b16 {%0,%1,%2,%3}, [%4];"
                 : "=r"(r0), "=r"(r1), "=r"(r2), "=r"(r3) : "r"(addr));
}

__global__ void __launch_bounds__(256, 2) mma_gemm_f16x2(
    const __half* __restrict__ Ahi,
    const __half* __restrict__ Bhi, const __half* __restrict__ Blo,
    float* __restrict__ C, int M, int N, int K)
{
    extern __shared__ __half sh[];
    const int tid  = threadIdx.x;
    const int wid  = tid >> 5;
    const int lane = tid & 31;
    const int g    = lane >> 2;
    const int tig  = lane & 3;
    const int bm   = blockIdx.x * 128;
    const int bn   = blockIdx.y * 128;
    const int wm   = (wid & 1) * 64;
    const int wn   = (wid >> 1) * 32;

    const uint32_t sbase = smem_to_u32(sh);

    const int a_r = lane & 15;
    const int a_c = (lane >> 4) * 8;
    const int b_r = (lane & 7) + ((lane >> 4) << 3);
    const int b_c = ((lane >> 3) & 1) * 8;

    float acc[4][4][4];
#pragma unroll
    for (int mt = 0; mt < 4; ++mt)
#pragma unroll
        for (int nt = 0; nt < 4; ++nt)
#pragma unroll
            for (int q = 0; q < 4; ++q) acc[mt][nt][q] = 0.f;

    const int NC = K >> 5;

    auto load_stage = [&](int s, int c) {
        const int kb = c * 32;
        const uint32_t stg = sbase + (uint32_t)s * STAGE_B;
#pragma unroll
        for (int i = 0; i < 2; ++i) {
            const int f   = tid + 256 * i;
            const int row = f >> 2;
            const int seg = (f & 3) * 8;
            const uint32_t doff = (uint32_t)(row * PADH + seg) * 2u;
            {
                const __half* p = Ahi + (size_t)(bm + row) * K + kb + seg;
                cp16(stg + doff, p);
            }
            {
                const int brow = bn + row;
                const int safe = (brow < N) ? brow : 0;
                const uint32_t sz = (brow < N) ? 16u : 0u;
                const __half* p  = Bhi + (size_t)safe * K + kb + seg;
                asm volatile("cp.async.cg.shared.global [%0], [%1], 16, %2;"
                             :: "r"(stg + (uint32_t)PLANE_H * 2u + doff), "l"(p), "r"(sz) : "memory");
                const __half* q2 = Blo + (size_t)safe * K + kb + seg;
                asm volatile("cp.async.cg.shared.global [%0], [%1], 16, %2;"
                             :: "r"(stg + (uint32_t)(2 * PLANE_H) * 2u + doff), "l"(q2), "r"(sz) : "memory");
            }
        }
        asm volatile("cp.async.commit_group;" ::: "memory");
    };

    auto compute_stage = [&](int s) {
        const uint32_t stg = sbase + (uint32_t)s * STAGE_B;
        const uint32_t aHi = stg;
        const uint32_t bHi = stg + (uint32_t)PLANE_H * 2u;
        const uint32_t bLo = stg + (uint32_t)(2 * PLANE_H) * 2u;
#pragma unroll
        for (int ks = 0; ks < 2; ++ks) {
            const int k0 = ks * 16;
            uint32_t ah[4][4], bh[4][2], bl[4][2];
#pragma unroll
            for (int p = 0; p < 2; ++p) {
                const uint32_t off = (uint32_t)((wn + p * 16 + b_r) * PADH + k0 + b_c) * 2u;
                ldsm4(bh[2*p][0], bh[2*p][1], bh[2*p+1][0], bh[2*p+1][1], bHi + off);
                ldsm4(bl[2*p][0], bl[2*p][1], bl[2*p+1][0], bl[2*p+1][1], bLo + off);
            }
#pragma unroll
            for (int mt = 0; mt < 4; ++mt) {
                const uint32_t off = (uint32_t)((wm + mt * 16 + a_r) * PADH + k0 + a_c) * 2u;
                ldsm4(ah[mt][0], ah[mt][1], ah[mt][2], ah[mt][3], aHi + off);
            }
#pragma unroll
            for (int mt = 0; mt < 4; ++mt)
#pragma unroll
                for (int nt = 0; nt < 4; ++nt)
                    mma16816(acc[mt][nt], ah[mt], bh[nt]);
#pragma unroll
            for (int mt = 0; mt < 4; ++mt)
#pragma unroll
                for (int nt = 0; nt < 4; ++nt)
                    mma16816(acc[mt][nt], ah[mt], bl[nt]);
        }
    };

    load_stage(0, 0);
    load_stage(1, 1);
    for (int c = 0; c < NC; ++c) {
        if (c + 2 < NC) {
            asm volatile("cp.async.wait_group 1;" ::: "memory");
        } else {
            asm volatile("cp.async.wait_group 0;" ::: "memory");
        }
        __syncthreads();
        if (c + 2 < NC) load_stage((c + 2) % 3, c + 2);
        compute_stage(c % 3);
    }

#pragma unroll
    for (int mt = 0; mt < 4; ++mt) {
        const int row0 = bm + wm + mt * 16 + g;
#pragma unroll
        for (int nt = 0; nt < 4; ++nt) {
            const int col = bn + wn + nt * 8 + tig * 2;
            if (col < N) {
                *(float2*)(C + (size_t)row0 * N + col)       = make_float2(acc[mt][nt][0], acc[mt][nt][1]);
                *(float2*)(C + (size_t)(row0 + 8) * N + col) = make_float2(acc[mt][nt][2], acc[mt][nt][3]);
            }
        }
    }
}

// ---------------- depthwise causal conv (width 4) + SiLU ----------------
__global__ void __launch_bounds__(256) conv_silu_kernel(
    const float* __restrict__ cw, const float* __restrict__ cb)
{
    const int c  = blockIdx.x * 256 + threadIdx.x;
    const int b  = blockIdx.z;
    const int t0 = blockIdx.y * 32;

    const float w0 = cw[c*4+0], w1 = cw[c*4+1], w2 = cw[c*4+2], w3 = cw[c*4+3];
    const float bias = cb[c];

    const float* base = g_zx + ((size_t)b * TLEN) * D_IN_PROJ + D_INNER + c;
    float* ob = g_xbc + ((size_t)b * TLEN) * CONV_DIM + c;

    float x0 = (t0 >= 3) ? base[(size_t)(t0-3) * D_IN_PROJ] : 0.f;
    float x1 = (t0 >= 2) ? base[(size_t)(t0-2) * D_IN_PROJ] : 0.f;
    float x2 = (t0 >= 1) ? base[(size_t)(t0-1) * D_IN_PROJ] : 0.f;

    for (int t = t0; t < t0 + 32; ++t) {
        const float x3 = base[(size_t)t * D_IN_PROJ];
        const float v  = bias + x0*w0 + x1*w1 + x2*w2 + x3*w3;
        ob[(size_t)t * CONV_DIM] = v / (1.f + expf(-v));
        x0 = x1; x1 = x2; x2 = x3;
    }
}

// ---------------- segmented scan pass A: double-buffered cp.async staging ----------------
#define SCAN_TC 8
#define NCHUNK (TSEG / SCAN_TC)   /* 16 */

__device__ __forceinline__ float softplus1(float raw) {
    return (raw > 20.f) ? raw : log1pf(expf(raw));
}

__global__ void __launch_bounds__(128) scan_seg_kernel(
    const float* __restrict__ dt_bias, const float* __restrict__ A_log,
    const float* __restrict__ Dskip)
{
    const int h   = blockIdx.x;
    const int b   = blockIdx.y;
    const int s   = blockIdx.z;
    const int tid = threadIdx.x;
    const int p    = tid >> 1;
    const int half = tid & 1;
    const int nb   = half * 64;

    __shared__ __align__(16) float sB[2][SCAN_TC][128];
    __shared__ __align__(16) float sC[2][SCAN_TC][128];
    __shared__ __align__(16) float sX[2][SCAN_TC][64];
    __shared__ float sDA[2][SCAN_TC], sDT[2][SCAN_TC];
    __shared__ float sred[8];

    float4 hst[16];
#pragma unroll
    for (int q = 0; q < 16; ++q) hst[q] = make_float4(0.f,0.f,0.f,0.f);

    const float Acoef = -expf(A_log[h]);
    const float dtb   = dt_bias[h];
    const float dsk   = Dskip[h];

    const float* xbc_b    = g_xbc + (size_t)b * TLEN * CONV_DIM;
    const float* dtr_base = g_zx  + (size_t)b * TLEN * D_IN_PROJ + (D_INNER + CONV_DIM) + h;
    float*       y_base   = g_y   + (size_t)b * TLEN * D_INNER + h * HEADDIM;

    const int tbeg = s * TSEG;

    const uint32_t sB0 = smem_to_u32(&sB[0][0][0]);
    const uint32_t sC0 = smem_to_u32(&sC[0][0][0]);
    const uint32_t sX0 = smem_to_u32(&sX[0][0][0]);

    // stage one chunk (640 float4 = 5 per thread): B(32) C(32) X(16) per tl
    auto issue_chunk = [&](int buf, int t0) {
#pragma unroll
        for (int i = 0; i < 5; ++i) {
            const int f  = tid + 128 * i;     // 0..639
            const int tl = f / 80;
            const int r  = f % 80;
            const float* row0 = xbc_b + (size_t)t0 * CONV_DIM + (size_t)tl * CONV_DIM;
            if (r < 32) {
                cp16(sB0 + (uint32_t)(buf * SCAN_TC * 128 + tl * 128 + 4 * r) * 4u,
                     row0 + D_INNER + 4 * r);
            } else if (r < 64) {
                cp16(sC0 + (uint32_t)(buf * SCAN_TC * 128 + tl * 128 + 4 * (r - 32)) * 4u,
                     row0 + D_INNER + D_STATE + 4 * (r - 32));
            } else {
                cp16(sX0 + (uint32_t)(buf * SCAN_TC * 64 + tl * 64 + 4 * (r - 64)) * 4u,
                     row0 + h * HEADDIM + 4 * (r - 64));
            }
        }
        asm volatile("cp.async.commit_group;" ::: "memory");
    };

    float sumdt_part = 0.f;
    float dtCur = 0.f, dACur = 0.f, rawNext = 0.f;

    issue_chunk(0, tbeg);
    if (tid < SCAN_TC) {
        const float raw = dtr_base[(size_t)(tbeg + tid) * D_IN_PROJ] + dtb;
        dtCur = softplus1(raw);
        dACur = expf(dtCur * Acoef);
    }

    for (int c = 0; c < NCHUNK; ++c) {
        const int cur = c & 1;
        const int t0  = tbeg + c * SCAN_TC;

        if (tid < SCAN_TC && c + 1 < NCHUNK)
            rawNext = dtr_base[(size_t)(t0 + SCAN_TC + tid) * D_IN_PROJ];

        asm volatile("cp.async.wait_group 0;" ::: "memory");
        if (tid < SCAN_TC) {
            sDT[cur][tid] = dtCur;
            sDA[cur][tid] = dACur;
            sumdt_part += dtCur;
        }
        __syncthreads();

        if (c + 1 < NCHUNK) issue_chunk(1 - cur, t0 + SCAN_TC);

#pragma unroll
        for (int tl = 0; tl < SCAN_TC; ++tl) {
            const float dA  = sDA[cur][tl];
            const float dtx = sDT[cur][tl] * sX[cur][tl][p];
            const float4* B4 = (const float4*)&sB[cur][tl][nb];
            const float4* C4 = (const float4*)&sC[cur][tl][nb];
            float y0 = 0.f, y1 = 0.f, y2 = 0.f, y3 = 0.f;
#pragma unroll
            for (int q = 0; q < 16; ++q) {
                const float4 bb = B4[q];
                const float4 cc = C4[q];
                hst[q].x = hst[q].x * dA + dtx * bb.x;  y0 += hst[q].x * cc.x;
                hst[q].y = hst[q].y * dA + dtx * bb.y;  y1 += hst[q].y * cc.y;
                hst[q].z = hst[q].z * dA + dtx * bb.z;  y2 += hst[q].z * cc.z;
                hst[q].w = hst[q].w * dA + dtx * bb.w;  y3 += hst[q].w * cc.w;
            }
            float y = (y0 + y1) + (y2 + y3);
            y += __shfl_xor_sync(0xffffffffu, y, 1);
            if (half == 0) {
                y += dsk * sX[cur][tl][p];
                y_base[(size_t)(t0 + tl) * D_INNER + p] = y;
            }
        }

        if (tid < SCAN_TC && c + 1 < NCHUNK) {
            dtCur = softplus1(rawNext + dtb);
            dACur = expf(dtCur * Acoef);
        }
        __syncthreads();   // protect sDA/sDT[cur] + buffer reuse pacing
    }

    float4* dst = (float4*)(g_hseg + ((size_t)((b * NHEADS + h) * SSEG + s)) * HSTATE
                            + p * D_STATE + nb);
#pragma unroll
    for (int q = 0; q < 16; ++q) dst[q] = hst[q];

    if (tid < 8) sred[tid] = sumdt_part;
    __syncthreads();
    if (tid == 0) {
        float t = 0.f;
#pragma unroll
        for (int i = 0; i < 8; ++i) t += sred[i];
        g_sumdt[(b * NHEADS + h) * SSEG + s] = t;
    }
}

// ---------------- pass B: sequential combine of segment boundary states ----------------
__global__ void __launch_bounds__(256) seg_combine_kernel(const float* __restrict__ A_log)
{
    const int bh  = blockIdx.x;
    const int h   = bh & (NHEADS - 1);
    const int tid = threadIdx.x;
    const float Acoef = -expf(A_log[h]);

    float4 carry[8];
#pragma unroll
    for (int i = 0; i < 8; ++i) carry[i] = make_float4(0.f,0.f,0.f,0.f);

    float* base = g_hseg + (size_t)bh * SSEG * HSTATE + tid * 32;
#pragma unroll
    for (int s = 0; s < SSEG; ++s) {
        const float P = expf(Acoef * g_sumdt[bh * SSEG + s]);
        float4* slot = (float4*)(base + (size_t)s * HSTATE);
#pragma unroll
        for (int i = 0; i < 8; ++i) {
            const float4 hend = slot[i];
            const float4 old  = carry[i];
            slot[i] = old;
            carry[i].x = P * old.x + hend.x;
            carry[i].y = P * old.y + hend.y;
            carry[i].z = P * old.z + hend.z;
            carry[i].w = P * old.w + hend.w;
        }
    }
}

// ---------------- pass C: y_t += prefix_t * (C_t . Hstart), double-buffered ----------------
__global__ void __launch_bounds__(128) seg_correct_kernel(
    const float* __restrict__ dt_bias, const float* __restrict__ A_log)
{
    const int h   = blockIdx.x;
    const int b   = blockIdx.y;
    const int s   = blockIdx.z + 1;
    const int tid = threadIdx.x;
    const int p    = tid >> 1;
    const int half = tid & 1;
    const int nb   = half * 64;

    __shared__ __align__(16) float sC[2][SCAN_TC][128];
    __shared__ float sDA[2][SCAN_TC];

    float4 hs[16];
    const float4* src = (const float4*)(g_hseg + ((size_t)((b * NHEADS + h) * SSEG + s)) * HSTATE
                                        + p * D_STATE + nb);
#pragma unroll
    for (int q = 0; q < 16; ++q) hs[q] = src[q];

    const float Acoef = -expf(A_log[h]);
    const float dtb   = dt_bias[h];

    const float* xbc_b    = g_xbc + (size_t)b * TLEN * CONV_DIM;
    const float* dtr_base = g_zx  + (size_t)b * TLEN * D_IN_PROJ + (D_INNER + CONV_DIM) + h;
    float*       y_base   = g_y   + (size_t)b * TLEN * D_INNER + h * HEADDIM;

    const int tbeg = s * TSEG;
    const uint32_t sC0 = smem_to_u32(&sC[0][0][0]);

    auto issue_chunk = [&](int buf, int t0) {
#pragma unroll
        for (int i = 0; i < 2; ++i) {
            const int f  = tid + 128 * i;     // 0..255
            const int tl = f >> 5;
            const int r  = f & 31;
            const float* row0 = xbc_b + (size_t)(t0 + tl) * CONV_DIM;
            cp16(sC0 + (uint32_t)(buf * SCAN_TC * 128 + tl * 128 + 4 * r) * 4u,
                 row0 + D_INNER + D_STATE + 4 * r);
        }
        asm volatile("cp.async.commit_group;" ::: "memory");
    };

    float dACur = 0.f, rawNext = 0.f;
    issue_chunk(0, tbeg);
    if (tid < SCAN_TC) {
        const float raw = dtr_base[(size_t)(tbeg + tid) * D_IN_PROJ] + dtb;
        dACur = expf(softplus1(raw) * Acoef);
    }

    float carryP = 1.f;
    for (int c = 0; c < NCHUNK; ++c) {
        const int cur = c & 1;
        const int t0  = tbeg + c * SCAN_TC;

        if (tid < SCAN_TC && c + 1 < NCHUNK)
            rawNext = dtr_base[(size_t)(t0 + SCAN_TC + tid) * D_IN_PROJ];

        asm volatile("cp.async.wait_group 0;" ::: "memory");
        if (tid < SCAN_TC) sDA[cur][tid] = dACur;
        __syncthreads();

        if (c + 1 < NCHUNK) issue_chunk(1 - cur, t0 + SCAN_TC);

        float pref = carryP;
#pragma unroll
        for (int tl = 0; tl < SCAN_TC; ++tl) {
            pref *= sDA[cur][tl];
            const float4* C4 = (const float4*)&sC[cur][tl][nb];
            float d0 = 0.f, d1 = 0.f, d2 = 0.f, d3 = 0.f;
#pragma unroll
            for (int q = 0; q < 16; ++q) {
                const float4 cc = C4[q];
                d0 += hs[q].x * cc.x;  d1 += hs[q].y * cc.y;
                d2 += hs[q].z * cc.z;  d3 += hs[q].w * cc.w;
            }
            float dot = (d0 + d1) + (d2 + d3);
            dot += __shfl_xor_sync(0xffffffffu, dot, 1);
            if (half == 0)
                y_base[(size_t)(t0 + tl) * D_INNER + p] += pref * dot;
        }
        carryP = pref;

        if (tid < SCAN_TC && c + 1 < NCHUNK)
            dACur = expf(softplus1(rawNext + dtb) * Acoef);
        __syncthreads();
    }
}

// ---------------- gate + RMSNorm, emits fp16 hi plane directly ----------------
__global__ void __launch_bounds__(256) gate_norm_cvt_kernel(
    const float* __restrict__ nw, __half* __restrict__ yhi)
{
    const int row = blockIdx.x;
    const int tid = threadIdx.x;
    const float* zrow = g_zx + (size_t)row * D_IN_PROJ;
    const float* yrow = g_y  + (size_t)row * D_INNER;

    float g[16];
    float ss = 0.f;
#pragma unroll
    for (int i = 0; i < 4; ++i) {
        const int e = i * 1024 + tid * 4;
        const float4 yv = *(const float4*)(yrow + e);
        const float4 zv = *(const float4*)(zrow + e);
        float g0 = yv.x * (zv.x / (1.f + expf(-zv.x)));
        float g1 = yv.y * (zv.y / (1.f + expf(-zv.y)));
        float g2 = yv.z * (zv.z / (1.f + expf(-zv.z)));
        float g3 = yv.w * (zv.w / (1.f + expf(-zv.w)));
        g[i*4+0] = g0; g[i*4+1] = g1; g[i*4+2] = g2; g[i*4+3] = g3;
        ss += g0*g0 + g1*g1 + g2*g2 + g3*g3;
    }

    ss += __shfl_xor_sync(0xffffffffu, ss, 16);
    ss += __shfl_xor_sync(0xffffffffu, ss, 8);
    ss += __shfl_xor_sync(0xffffffffu, ss, 4);
    ss += __shfl_xor_sync(0xffffffffu, ss, 2);
    ss += __shfl_xor_sync(0xffffffffu, ss, 1);
    __shared__ float red[8];
    if ((tid & 31) == 0) red[tid >> 5] = ss;
    __syncthreads();
    float tot = 0.f;
#pragma unroll
    for (int w = 0; w < 8; ++w) tot += red[w];

    const float scale = rsqrtf(tot / (float)D_INNER + RMS_EPS);
#pragma unroll
    for (int i = 0; i < 4; ++i) {
        const int e = i * 1024 + tid * 4;
        const float v0 = g[i*4+0] * scale * nw[e+0];
        const float v1 = g[i*4+1] * scale * nw[e+1];
        const float v2 = g[i*4+2] * scale * nw[e+2];
        const float v3 = g[i*4+3] * scale * nw[e+3];
        __half2* hp = (__half2*)(yhi + (size_t)row * D_INNER + e);
        hp[0] = __halves2half2(__float2half_rn(v0), __float2half_rn(v1));
        hp[1] = __halves2half2(__float2half_rn(v2), __float2half_rn(v3));
    }
}

// ---------------- launch ----------------
extern "C" void kernel_launch(void* const* d_in, const int* in_sizes, int n_in,
                              void* d_out, int out_size)
{
    const float* x          = (const float*)d_in[0];
    const float* in_proj_w  = (const float*)d_in[3];
    const float* conv_w     = (const float*)d_in[4];
    const float* conv_b     = (const float*)d_in[5];
    const float* dt_bias    = (const float*)d_in[6];
    const float* A_log      = (const float*)d_in[7];
    const float* Dskip      = (const float*)d_in[8];
    const float* norm_w     = (const float*)d_in[9];
    const float* out_proj_w = (const float*)d_in[10];
    float* out = (float*)d_out;

    float *zx;
    __half *xc, *w1c, *yc, *w2c;
    cudaGetSymbolAddress((void**)&zx,  g_zx);
    cudaGetSymbolAddress((void**)&xc,  g_xc);
    cudaGetSymbolAddress((void**)&w1c, g_w1c);
    cudaGetSymbolAddress((void**)&yc,  g_yc);
    cudaGetSymbolAddress((void**)&w2c, g_w2c);

    cudaFuncSetAttribute(mma_gemm_f16x2,
                         cudaFuncAttributeMaxDynamicSharedMemorySize, GEMM_SMEM);

    // 0) convert: x -> hi plane; weights -> hi+lo planes
    {
        const int nx = NTOK * D_MODEL / 4;
        cvt_hi_kernel<<<(nx + 255) / 256, 256>>>(x, xc, nx);
        const int nw1 = D_IN_PROJ * D_MODEL / 4;
        cvt_f16x2_kernel<<<(nw1 + 255) / 256, 256>>>(in_proj_w, w1c, w1c + (size_t)D_IN_PROJ * D_MODEL, nw1);
        const int nw2 = D_MODEL * D_INNER / 4;
        cvt_f16x2_kernel<<<(nw2 + 255) / 256, 256>>>(out_proj_w, w2c, w2c + (size_t)D_MODEL * D_INNER, nw2);
    }

    // 1) in_proj: zx[4096, 8512] = x * W1^T
    {
        dim3 grid(NTOK / 128, (D_IN_PROJ + 127) / 128);
        mma_gemm_f16x2<<<grid, 256, GEMM_SMEM>>>(
            xc, w1c, w1c + (size_t)D_IN_PROJ * D_MODEL,
            zx, NTOK, D_IN_PROJ, D_MODEL);
    }
    // 2) conv + silu
    {
        dim3 grid(CONV_DIM / 256, TLEN / 32, BATCH);
        conv_silu_kernel<<<grid, 256>>>(conv_w, conv_b);
    }
    // 3) segmented SSM scan: local scans -> combine -> correct
    {
        dim3 gridA(NHEADS, BATCH, SSEG);
        scan_seg_kernel<<<gridA, 128>>>(dt_bias, A_log, Dskip);
        seg_combine_kernel<<<BATCH * NHEADS, 256>>>(A_log);
        dim3 gridC(NHEADS, BATCH, SSEG - 1);
        seg_correct_kernel<<<gridC, 128>>>(dt_bias, A_log);
    }
    // 4) gate + RMSNorm + fp16 hi (fused)
    gate_norm_cvt_kernel<<<NTOK, 256>>>(norm_w, yc);

    // 5) out_proj: out[4096, 2048] = y * W2^T
    {
        dim3 grid(NTOK / 128, D_MODEL / 128);
        mma_gemm_f16x2<<<grid, 256, GEMM_SMEM>>>(
            yc, w2c, w2c + (size_t)D_MODEL * D_INNER,
            out, NTOK, D_MODEL, D_INNER);
    }
}

// round 13
// speedup vs baseline: 1.3436x; 1.2517x over previous
#include <cuda_runtime.h>
#include <cuda_fp16.h>
#include <math.h>
#include <stdint.h>

#define D_MODEL   2048
#define D_INNER   4096
#define D_STATE   128
#define HEADDIM   64
#define NHEADS    64
#define CONV_DIM  4352     /* D_INNER + 2*D_STATE */
#define D_IN_PROJ 8512     /* 2*D_INNER + 2*D_STATE + NHEADS */
#define BATCH     2
#define TLEN      2048
#define NTOK      (BATCH*TLEN)   /* 4096 */
#define RMS_EPS   1e-5f

#define SSEG 16
#define TSEG (TLEN / SSEG)       /* 128 = SSD chunk */
#define HSTATE (HEADDIM * D_STATE)  /* 8192 */

// ---------------- scratch (device globals; no allocs allowed) ----------------
__device__ float g_zx [(size_t)NTOK * D_IN_PROJ];
__device__ float g_xbc[(size_t)NTOK * CONV_DIM];
__device__ float g_y  [(size_t)NTOK * D_INNER];
__device__ float g_hseg[(size_t)BATCH * NHEADS * SSEG * HSTATE];
__device__ float g_sumdt[BATCH * NHEADS * SSEG];

__device__ __half g_xc [(size_t)NTOK * D_MODEL];
__device__ __half g_w1c[(size_t)2 * D_IN_PROJ * D_MODEL];
__device__ __half g_yc [(size_t)NTOK * D_INNER];
__device__ __half g_w2c[(size_t)2 * D_MODEL * D_INNER];

__device__ __forceinline__ uint32_t smem_to_u32(const void* p) {
    uint32_t a;
    asm("{ .reg .u64 t; cvta.to.shared.u64 t, %1; cvt.u32.u64 %0, t; }" : "=r"(a) : "l"(p));
    return a;
}
__device__ __forceinline__ float softplus1(float raw) {
    return (raw > 20.f) ? raw : log1pf(expf(raw));
}

// ---------------- fp32 -> fp16 hi plane only ----------------
__global__ void __launch_bounds__(256) cvt_hi_kernel(
    const float* __restrict__ src, __half* __restrict__ hi, int n4)
{
    const int i = blockIdx.x * 256 + threadIdx.x;
    if (i >= n4) return;
    const float4 v = ((const float4*)src)[i];
    __half2* hp = (__half2*)(hi + (size_t)i * 4);
    hp[0] = __halves2half2(__float2half_rn(v.x), __float2half_rn(v.y));
    hp[1] = __halves2half2(__float2half_rn(v.z), __float2half_rn(v.w));
}

// ---------------- fp32 -> (hi, lo) fp16 planes (weights) ----------------
__global__ void __launch_bounds__(256) cvt_f16x2_kernel(
    const float* __restrict__ src, __half* __restrict__ hi, __half* __restrict__ lo, int n4)
{
    const int i = blockIdx.x * 256 + threadIdx.x;
    if (i >= n4) return;
    const float4 v = ((const float4*)src)[i];
    __half h0 = __float2half_rn(v.x), h1 = __float2half_rn(v.y);
    __half h2 = __float2half_rn(v.z), h3 = __float2half_rn(v.w);
    __half l0 = __float2half_rn(v.x - __half2float(h0));
    __half l1 = __float2half_rn(v.y - __half2float(h1));
    __half l2 = __float2half_rn(v.z - __half2float(h2));
    __half l3 = __float2half_rn(v.w - __half2float(h3));
    __half2* hp = (__half2*)(hi + (size_t)i * 4);
    __half2* lp = (__half2*)(lo + (size_t)i * 4);
    hp[0] = __halves2half2(h0, h1); hp[1] = __halves2half2(h2, h3);
    lp[0] = __halves2half2(l0, l1); lp[1] = __halves2half2(l2, l3);
}

// ---------------- shared MMA helpers ----------------
__device__ __forceinline__ void mma16816(float* c, const uint32_t* a, const uint32_t* b) {
    asm volatile(
        "mma.sync.aligned.m16n8k16.row.col.f32.f16.f16.f32 "
        "{%0,%1,%2,%3}, {%4,%5,%6,%7}, {%8,%9}, {%0,%1,%2,%3};"
        : "+f"(c[0]), "+f"(c[1]), "+f"(c[2]), "+f"(c[3])
        : "r"(a[0]), "r"(a[1]), "r"(a[2]), "r"(a[3]), "r"(b[0]), "r"(b[1]));
}
__device__ __forceinline__ void ldsm4(uint32_t& r0, uint32_t& r1, uint32_t& r2, uint32_t& r3,
                                      uint32_t addr) {
    asm volatile("ldmatrix.sync.aligned.m8n8.x4.shared.b16 {%0,%1,%2,%3}, [%4];"
                 : "=r"(r0), "=r"(r1), "=r"(r2), "=r"(r3) : "r"(addr));
}

// ======== fp16x2 GEMM: 128x128 tile, 3-stage pipeline, 2 CTAs/SM (frozen) ========
#define PADH 40
#define PLANE_H (128 * PADH)
#define STAGE_B (3 * PLANE_H * 2)
#define GEMM_SMEM (3 * STAGE_B)

__global__ void __launch_bounds__(256, 2) mma_gemm_f16x2(
    const __half* __restrict__ Ahi,
    const __half* __restrict__ Bhi, const __half* __restrict__ Blo,
    float* __restrict__ C, int M, int N, int K)
{
    extern __shared__ __half sh[];
    const int tid  = threadIdx.x;
    const int wid  = tid >> 5;
    const int lane = tid & 31;
    const int g    = lane >> 2;
    const int tig  = lane & 3;
    const int bm   = blockIdx.x * 128;
    const int bn   = blockIdx.y * 128;
    const int wm   = (wid & 1) * 64;
    const int wn   = (wid >> 1) * 32;

    const uint32_t sbase = smem_to_u32(sh);

    const int a_r = lane & 15;
    const int a_c = (lane >> 4) * 8;
    const int b_r = (lane & 7) + ((lane >> 4) << 3);
    const int b_c = ((lane >> 3) & 1) * 8;

    float acc[4][4][4];
#pragma unroll
    for (int mt = 0; mt < 4; ++mt)
#pragma unroll
        for (int nt = 0; nt < 4; ++nt)
#pragma unroll
            for (int q = 0; q < 4; ++q) acc[mt][nt][q] = 0.f;

    const int NC = K >> 5;

    auto load_stage = [&](int s, int c) {
        const int kb = c * 32;
        const uint32_t stg = sbase + (uint32_t)s * STAGE_B;
#pragma unroll
        for (int i = 0; i < 2; ++i) {
            const int f   = tid + 256 * i;
            const int row = f >> 2;
            const int seg = (f & 3) * 8;
            const uint32_t doff = (uint32_t)(row * PADH + seg) * 2u;
            {
                const __half* p = Ahi + (size_t)(bm + row) * K + kb + seg;
                asm volatile("cp.async.cg.shared.global [%0], [%1], 16;"
                             :: "r"(stg + doff), "l"(p) : "memory");
            }
            {
                const int brow = bn + row;
                const int safe = (brow < N) ? brow : 0;
                const uint32_t sz = (brow < N) ? 16u : 0u;
                const __half* p  = Bhi + (size_t)safe * K + kb + seg;
                asm volatile("cp.async.cg.shared.global [%0], [%1], 16, %2;"
                             :: "r"(stg + (uint32_t)PLANE_H * 2u + doff), "l"(p), "r"(sz) : "memory");
                const __half* q2 = Blo + (size_t)safe * K + kb + seg;
                asm volatile("cp.async.cg.shared.global [%0], [%1], 16, %2;"
                             :: "r"(stg + (uint32_t)(2 * PLANE_H) * 2u + doff), "l"(q2), "r"(sz) : "memory");
            }
        }
        asm volatile("cp.async.commit_group;" ::: "memory");
    };

    auto compute_stage = [&](int s) {
        const uint32_t stg = sbase + (uint32_t)s * STAGE_B;
        const uint32_t aHi = stg;
        const uint32_t bHi = stg + (uint32_t)PLANE_H * 2u;
        const uint32_t bLo = stg + (uint32_t)(2 * PLANE_H) * 2u;
#pragma unroll
        for (int ks = 0; ks < 2; ++ks) {
            const int k0 = ks * 16;
            uint32_t ah[4][4], bh[4][2], bl[4][2];
#pragma unroll
            for (int p = 0; p < 2; ++p) {
                const uint32_t off = (uint32_t)((wn + p * 16 + b_r) * PADH + k0 + b_c) * 2u;
                ldsm4(bh[2*p][0], bh[2*p][1], bh[2*p+1][0], bh[2*p+1][1], bHi + off);
                ldsm4(bl[2*p][0], bl[2*p][1], bl[2*p+1][0], bl[2*p+1][1], bLo + off);
            }
#pragma unroll
            for (int mt = 0; mt < 4; ++mt) {
                const uint32_t off = (uint32_t)((wm + mt * 16 + a_r) * PADH + k0 + a_c) * 2u;
                ldsm4(ah[mt][0], ah[mt][1], ah[mt][2], ah[mt][3], aHi + off);
            }
#pragma unroll
            for (int mt = 0; mt < 4; ++mt)
#pragma unroll
                for (int nt = 0; nt < 4; ++nt)
                    mma16816(acc[mt][nt], ah[mt], bh[nt]);
#pragma unroll
            for (int mt = 0; mt < 4; ++mt)
#pragma unroll
                for (int nt = 0; nt < 4; ++nt)
                    mma16816(acc[mt][nt], ah[mt], bl[nt]);
        }
    };

    load_stage(0, 0);
    load_stage(1, 1);
    for (int c = 0; c < NC; ++c) {
        if (c + 2 < NC) {
            asm volatile("cp.async.wait_group 1;" ::: "memory");
        } else {
            asm volatile("cp.async.wait_group 0;" ::: "memory");
        }
        __syncthreads();
        if (c + 2 < NC) load_stage((c + 2) % 3, c + 2);
        compute_stage(c % 3);
    }

#pragma unroll
    for (int mt = 0; mt < 4; ++mt) {
        const int row0 = bm + wm + mt * 16 + g;
#pragma unroll
        for (int nt = 0; nt < 4; ++nt) {
            const int col = bn + wn + nt * 8 + tig * 2;
            if (col < N) {
                *(float2*)(C + (size_t)row0 * N + col)       = make_float2(acc[mt][nt][0], acc[mt][nt][1]);
                *(float2*)(C + (size_t)(row0 + 8) * N + col) = make_float2(acc[mt][nt][2], acc[mt][nt][3]);
            }
        }
    }
}

// ---------------- depthwise causal conv (width 4) + SiLU ----------------
__global__ void __launch_bounds__(256) conv_silu_kernel(
    const float* __restrict__ cw, const float* __restrict__ cb)
{
    const int c  = blockIdx.x * 256 + threadIdx.x;
    const int b  = blockIdx.z;
    const int t0 = blockIdx.y * 32;

    const float w0 = cw[c*4+0], w1 = cw[c*4+1], w2 = cw[c*4+2], w3 = cw[c*4+3];
    const float bias = cb[c];

    const float* base = g_zx + ((size_t)b * TLEN) * D_IN_PROJ + D_INNER + c;
    float* ob = g_xbc + ((size_t)b * TLEN) * CONV_DIM + c;

    float x0 = (t0 >= 3) ? base[(size_t)(t0-3) * D_IN_PROJ] : 0.f;
    float x1 = (t0 >= 2) ? base[(size_t)(t0-2) * D_IN_PROJ] : 0.f;
    float x2 = (t0 >= 1) ? base[(size_t)(t0-1) * D_IN_PROJ] : 0.f;

    for (int t = t0; t < t0 + 32; ++t) {
        const float x3 = base[(size_t)t * D_IN_PROJ];
        const float v  = bias + x0*w0 + x1*w1 + x2*w2 + x3*w3;
        ob[(size_t)t * CONV_DIM] = v / (1.f + expf(-v));
        x0 = x1; x1 = x2; x2 = x3;
    }
}

// ======================= SSD chunked scan on tensor cores =======================
// Per (b,h,chunk=128): Y_intra = (L o (C B^T)) X  and  S^T = Xs^T B  via fp16 MMA.
// L[i][j] = dt_j * prod_{k=j+1..i} dA_k (causal), built multiplicatively.
// Xs[j] = dt_j * exp(cumA_end - cumA_j) * x_j.
#define PADN 136                          /* halves per 128-wide row */
#define OFF_CT  0
#define OFF_BT  17408
#define OFF_BT2 34816
#define OFF_L   52224
#define OFF_XT  69632
#define OFF_XST 78336
#define SSD_FLT 87040                     /* halves before float area */
#define SSD_SMEM (SSD_FLT * 2 + 1600)

__global__ void __launch_bounds__(256, 1) ssd_chunk_kernel(
    const float* __restrict__ dt_bias, const float* __restrict__ A_log,
    const float* __restrict__ Dskip)
{
    extern __shared__ __half sh[];
    float* fb   = (float*)(sh + SSD_FLT);
    float* sdt  = fb;          // [128]
    float* sda  = fb + 128;    // [128]
    float* scum = fb + 256;    // [128] inclusive cumsum of dt
    float* fw   = fb + 384;    // [4]

    const int h = blockIdx.x, b = blockIdx.y, s = blockIdx.z;
    const int tid = threadIdx.x;
    const int wid = tid >> 5;
    const int lane = tid & 31;
    const int g   = lane >> 2;
    const int tig = lane & 3;
    const int a_r = lane & 15;
    const int a_c = (lane >> 4) * 8;
    const int b_r = (lane & 7) + ((lane >> 4) << 3);
    const int b_c = ((lane >> 3) & 1) * 8;

    const float Acoef = -expf(A_log[h]);
    const float dtb   = dt_bias[h];
    const float dsk   = Dskip[h];
    const int   t0    = s * TSEG;
    const size_t rbase = (size_t)(b * TLEN + t0);

    // ---- phase 0a: dt, dA, prefix-scan of dt ----
    float vscan = 0.f;
    if (tid < 128) {
        const float raw = g_zx[(rbase + tid) * D_IN_PROJ + (D_INNER + CONV_DIM) + h] + dtb;
        const float dt  = softplus1(raw);
        sdt[tid] = dt;
        sda[tid] = expf(dt * Acoef);
        float v = dt;
#pragma unroll
        for (int o = 1; o < 32; o <<= 1) {
            const float t = __shfl_up_sync(0xffffffffu, v, o);
            if (lane >= o) v += t;
        }
        vscan = v;
        if (lane == 31) fw[wid] = v;
    }
    __syncthreads();
    if (tid < 128) {
        float off = 0.f;
        for (int w = 0; w < wid; ++w) off += fw[w];
        scum[tid] = off + vscan;
    }
    __syncthreads();

    const float cumTot = scum[127];
    if (tid == 0) g_sumdt[(b * NHEADS + h) * SSEG + s] = cumTot;

    // ---- phase 0b: stage tiles (C,B,B^T) + X (plain, scaled-transposed) + L ----
    {
        const int t  = tid >> 1;
        const int sg = (tid & 1) * 64;
        const float* row = g_xbc + (rbase + t) * CONV_DIM + D_INNER;
#pragma unroll
        for (int u = 0; u < 16; ++u) {
            const float4 bb = *(const float4*)(row + sg + 4 * u);
            __half2* bp = (__half2*)(sh + OFF_BT + t * PADN + sg + 4 * u);
            bp[0] = __floats2half2_rn(bb.x, bb.y);
            bp[1] = __floats2half2_rn(bb.z, bb.w);
            sh[OFF_BT2 + (sg + 4*u + 0) * PADN + t] = __float2half_rn(bb.x);
            sh[OFF_BT2 + (sg + 4*u + 1) * PADN + t] = __float2half_rn(bb.y);
            sh[OFF_BT2 + (sg + 4*u + 2) * PADN + t] = __float2half_rn(bb.z);
            sh[OFF_BT2 + (sg + 4*u + 3) * PADN + t] = __float2half_rn(bb.w);
            const float4 cc = *(const float4*)(row + D_STATE + sg + 4 * u);
            __half2* cp = (__half2*)(sh + OFF_CT + t * PADN + sg + 4 * u);
            cp[0] = __floats2half2_rn(cc.x, cc.y);
            cp[1] = __floats2half2_rn(cc.z, cc.w);
        }
    }
    if (tid < 128) {
        const int t = tid;
        const float wj = sdt[t] * expf(Acoef * (cumTot - scum[t]));
        const float* xrow = g_xbc + (rbase + t) * CONV_DIM + h * HEADDIM;
#pragma unroll
        for (int u = 0; u < 16; ++u) {
            const float4 xv = *(const float4*)(xrow + 4 * u);
            const int p = 4 * u;
            sh[OFF_XT  + (p+0) * PADN + t] = __float2half_rn(xv.x);
            sh[OFF_XT  + (p+1) * PADN + t] = __float2half_rn(xv.y);
            sh[OFF_XT  + (p+2) * PADN + t] = __float2half_rn(xv.z);
            sh[OFF_XT  + (p+3) * PADN + t] = __float2half_rn(xv.w);
            sh[OFF_XST + (p+0) * PADN + t] = __float2half_rn(wj * xv.x);
            sh[OFF_XST + (p+1) * PADN + t] = __float2half_rn(wj * xv.y);
            sh[OFF_XST + (p+2) * PADN + t] = __float2half_rn(wj * xv.z);
            sh[OFF_XST + (p+3) * PADN + t] = __float2half_rn(wj * xv.w);
        }
        // L column j = tid, rows i ascending
        const int j = tid;
        const float dtj = sdt[j];
        float val = 0.f;
        for (int i = 0; i < 128; ++i) {
            val = (i == j) ? dtj : sda[i] * val;
            sh[OFF_L + i * PADN + j] = __float2half_rn(val);
        }
    }
    __syncthreads();

    const uint32_t sb   = smem_to_u32(sh);
    const uint32_t uCT  = sb + OFF_CT  * 2u;
    const uint32_t uBT  = sb + OFF_BT  * 2u;
    const uint32_t uBT2 = sb + OFF_BT2 * 2u;
    const uint32_t uXT  = sb + OFF_XT  * 2u;
    const uint32_t uXST = sb + OFF_XST * 2u;

    // ---- GEMM1: G = C @ B^T  (M=128 i, N=128 j, K=128 n) ----
    const int wm1 = wid * 16;
    float acc1[16][4];
#pragma unroll
    for (int nt = 0; nt < 16; ++nt)
#pragma unroll
        for (int q = 0; q < 4; ++q) acc1[nt][q] = 0.f;

#pragma unroll
    for (int ks = 0; ks < 8; ++ks) {
        const int k0 = ks * 16;
        uint32_t ah[4];
        ldsm4(ah[0], ah[1], ah[2], ah[3],
              uCT + (uint32_t)((wm1 + a_r) * PADN + k0 + a_c) * 2u);
        uint32_t bh[16][2];
#pragma unroll
        for (int p4 = 0; p4 < 8; ++p4)
            ldsm4(bh[2*p4][0], bh[2*p4][1], bh[2*p4+1][0], bh[2*p4+1][1],
                  uBT + (uint32_t)((p4 * 16 + b_r) * PADN + k0 + b_c) * 2u);
#pragma unroll
        for (int nt = 0; nt < 16; ++nt)
            mma16816(acc1[nt], ah, bh[nt]);
    }

    // ---- apply L, write Gp (reusing Ct region; warp-local rows) ----
    const int i0 = wm1 + g;
#pragma unroll
    for (int nt = 0; nt < 16; ++nt) {
        const int col = nt * 8 + tig * 2;
        const float2 f0 = __half22float2(*(__half2*)(sh + OFF_L + i0 * PADN + col));
        const float2 f1 = __half22float2(*(__half2*)(sh + OFF_L + (i0 + 8) * PADN + col));
        *(__half2*)(sh + OFF_CT + i0 * PADN + col)       = __floats2half2_rn(acc1[nt][0] * f0.x, acc1[nt][1] * f0.y);
        *(__half2*)(sh + OFF_CT + (i0 + 8) * PADN + col) = __floats2half2_rn(acc1[nt][2] * f1.x, acc1[nt][3] * f1.y);
    }
    __syncwarp();

    // ---- GEMM2: Y = Gp @ Xt^T  (M=128 i, N=64 p, K=128 j) ----
    float acc2[8][4];
#pragma unroll
    for (int nt = 0; nt < 8; ++nt)
#pragma unroll
        for (int q = 0; q < 4; ++q) acc2[nt][q] = 0.f;
#pragma unroll
    for (int ks = 0; ks < 8; ++ks) {
        const int k0 = ks * 16;
        uint32_t ah[4];
        ldsm4(ah[0], ah[1], ah[2], ah[3],
              uCT + (uint32_t)((wm1 + a_r) * PADN + k0 + a_c) * 2u);
        uint32_t bh[8][2];
#pragma unroll
        for (int p4 = 0; p4 < 4; ++p4)
            ldsm4(bh[2*p4][0], bh[2*p4][1], bh[2*p4+1][0], bh[2*p4+1][1],
                  uXT + (uint32_t)((p4 * 16 + b_r) * PADN + k0 + b_c) * 2u);
#pragma unroll
        for (int nt = 0; nt < 8; ++nt)
            mma16816(acc2[nt], ah, bh[nt]);
    }
    // Y epilogue: + Dskip * x, write g_y
    {
        const size_t r0 = rbase + i0;
        const size_t r1 = r0 + 8;
#pragma unroll
        for (int nt = 0; nt < 8; ++nt) {
            const int col = nt * 8 + tig * 2;
            const float2 x0 = *(const float2*)(g_xbc + r0 * CONV_DIM + h * HEADDIM + col);
            const float2 x1 = *(const float2*)(g_xbc + r1 * CONV_DIM + h * HEADDIM + col);
            *(float2*)(g_y + r0 * D_INNER + h * HEADDIM + col) =
                make_float2(acc2[nt][0] + dsk * x0.x, acc2[nt][1] + dsk * x0.y);
            *(float2*)(g_y + r1 * D_INNER + h * HEADDIM + col) =
                make_float2(acc2[nt][2] + dsk * x1.x, acc2[nt][3] + dsk * x1.y);
        }
    }

    // ---- GEMM3: S^T = Xst @ Bt2^T  (M=64 p, N=128 n, K=128 j) ----
    const int wm3 = (wid & 3) * 16;
    const int nb3 = (wid >> 2) * 64;
    float acc3[8][4];
#pragma unroll
    for (int nt = 0; nt < 8; ++nt)
#pragma unroll
        for (int q = 0; q < 4; ++q) acc3[nt][q] = 0.f;
#pragma unroll
    for (int ks = 0; ks < 8; ++ks) {
        const int k0 = ks * 16;
        uint32_t ah[4];
        ldsm4(ah[0], ah[1], ah[2], ah[3],
              uXST + (uint32_t)((wm3 + a_r) * PADN + k0 + a_c) * 2u);
        uint32_t bh[8][2];
#pragma unroll
        for (int p4 = 0; p4 < 4; ++p4)
            ldsm4(bh[2*p4][0], bh[2*p4][1], bh[2*p4+1][0], bh[2*p4+1][1],
                  uBT2 + (uint32_t)((nb3 + p4 * 16 + b_r) * PADN + k0 + b_c) * 2u);
#pragma unroll
        for (int nt = 0; nt < 8; ++nt)
            mma16816(acc3[nt], ah, bh[nt]);
    }
    {
        float* hbase = g_hseg + ((size_t)((b * NHEADS + h) * SSEG + s)) * HSTATE;
        const int p0 = wm3 + g;
#pragma unroll
        for (int nt = 0; nt < 8; ++nt) {
            const int n = nb3 + nt * 8 + tig * 2;
            *(float2*)(hbase + (size_t)p0 * D_STATE + n)       = make_float2(acc3[nt][0], acc3[nt][1]);
            *(float2*)(hbase + (size_t)(p0 + 8) * D_STATE + n) = make_float2(acc3[nt][2], acc3[nt][3]);
        }
    }
}

// ---------------- pass B: sequential combine of segment boundary states ----------------
__global__ void __launch_bounds__(256) seg_combine_kernel(const float* __restrict__ A_log)
{
    const int bh  = blockIdx.x;
    const int h   = bh & (NHEADS - 1);
    const int tid = threadIdx.x;
    const float Acoef = -expf(A_log[h]);

    float4 carry[8];
#pragma unroll
    for (int i = 0; i < 8; ++i) carry[i] = make_float4(0.f,0.f,0.f,0.f);

    float* base = g_hseg + (size_t)bh * SSEG * HSTATE + tid * 32;
#pragma unroll
    for (int s = 0; s < SSEG; ++s) {
        const float P = expf(Acoef * g_sumdt[bh * SSEG + s]);
        float4* slot = (float4*)(base + (size_t)s * HSTATE);
#pragma unroll
        for (int i = 0; i < 8; ++i) {
            const float4 hend = slot[i];
            const float4 old  = carry[i];
            slot[i] = old;
            carry[i].x = P * old.x + hend.x;
            carry[i].y = P * old.y + hend.y;
            carry[i].z = P * old.z + hend.z;
            carry[i].w = P * old.w + hend.w;
        }
    }
}

// ---------------- pass C (MMA): Y += (exp(cumA_i) C_i) @ Hstart^T ----------------
#define K3_CS 0
#define K3_HT 17408
#define K3_FLT 26112
#define K3_SMEM (K3_FLT * 2 + 600)

__global__ void __launch_bounds__(256, 1) ssd_correct_kernel(
    const float* __restrict__ dt_bias, const float* __restrict__ A_log)
{
    extern __shared__ __half sh[];
    float* fb   = (float*)(sh + K3_FLT);
    float* scum = fb;        // [128]
    float* fw   = fb + 128;  // [4]

    const int h = blockIdx.x, b = blockIdx.y, s = blockIdx.z + 1;
    const int tid = threadIdx.x;
    const int wid = tid >> 5;
    const int lane = tid & 31;
    const int g   = lane >> 2;
    const int tig = lane & 3;
    const int a_r = lane & 15;
    const int a_c = (lane >> 4) * 8;
    const int b_r = (lane & 7) + ((lane >> 4) << 3);
    const int b_c = ((lane >> 3) & 1) * 8;

    const float Acoef = -expf(A_log[h]);
    const float dtb   = dt_bias[h];
    const int   t0    = s * TSEG;
    const size_t rbase = (size_t)(b * TLEN + t0);

    float vscan = 0.f;
    if (tid < 128) {
        const float raw = g_zx[(rbase + tid) * D_IN_PROJ + (D_INNER + CONV_DIM) + h] + dtb;
        float v = softplus1(raw);
#pragma unroll
        for (int o = 1; o < 32; o <<= 1) {
            const float t = __shfl_up_sync(0xffffffffu, v, o);
            if (lane >= o) v += t;
        }
        vscan = v;
        if (lane == 31) fw[wid] = v;
    }
    __syncthreads();
    if (tid < 128) {
        float off = 0.f;
        for (int w = 0; w < wid; ++w) off += fw[w];
        scum[tid] = off + vscan;
    }
    __syncthreads();

    // stage Cs (row-scaled C) and Ht (Hstart fp32 -> fp16)
    {
        const int t  = tid >> 1;
        const int sg = (tid & 1) * 64;
        const float ri = expf(Acoef * scum[t]);
        const float* row = g_xbc + (rbase + t) * CONV_DIM + D_INNER + D_STATE;
#pragma unroll
        for (int u = 0; u < 16; ++u) {
            const float4 cc = *(const float4*)(row + sg + 4 * u);
            __half2* cp = (__half2*)(sh + K3_CS + t * PADN + sg + 4 * u);
            cp[0] = __floats2half2_rn(ri * cc.x, ri * cc.y);
            cp[1] = __floats2half2_rn(ri * cc.z, ri * cc.w);
        }
    }
    if (tid < 128) {
        const int p  = tid >> 1;
        const int sg = (tid & 1) * 64;
        const float* hrow = g_hseg + ((size_t)((b * NHEADS + h) * SSEG + s)) * HSTATE
                          + (size_t)p * D_STATE + sg;
#pragma unroll
        for (int u = 0; u < 16; ++u) {
            const float4 hv = *(const float4*)(hrow + 4 * u);
            __half2* hp = (__half2*)(sh + K3_HT + p * PADN + sg + 4 * u);
            hp[0] = __floats2half2_rn(hv.x, hv.y);
            hp[1] = __floats2half2_rn(hv.z, hv.w);
        }
    }
    __syncthreads();

    const uint32_t sb  = smem_to_u32(sh);
    const uint32_t uCS = sb + K3_CS * 2u;
    const uint32_t uHT = sb + K3_HT * 2u;

    const int wm = wid * 16;
    float acc[8][4];
#pragma unroll
    for (int nt = 0; nt < 8; ++nt)
#pragma unroll
        for (int q = 0; q < 4; ++q) acc[nt][q] = 0.f;

#pragma unroll
    for (int ks = 0; ks < 8; ++ks) {
        const int k0 = ks * 16;
        uint32_t ah[4];
        ldsm4(ah[0], ah[1], ah[2], ah[3],
              uCS + (uint32_t)((wm + a_r) * PADN + k0 + a_c) * 2u);
        uint32_t bh[8][2];
#pragma unroll
        for (int p4 = 0; p4 < 4; ++p4)
            ldsm4(bh[2*p4][0], bh[2*p4][1], bh[2*p4+1][0], bh[2*p4+1][1],
                  uHT + (uint32_t)((p4 * 16 + b_r) * PADN + k0 + b_c) * 2u);
#pragma unroll
        for (int nt = 0; nt < 8; ++nt)
            mma16816(acc[nt], ah, bh[nt]);
    }

    const int i0 = wm + g;
    const size_t r0 = rbase + i0;
    const size_t r1 = r0 + 8;
#pragma unroll
    for (int nt = 0; nt < 8; ++nt) {
        const int col = nt * 8 + tig * 2;
        float2 y0 = *(float2*)(g_y + r0 * D_INNER + h * HEADDIM + col);
        float2 y1 = *(float2*)(g_y + r1 * D_INNER + h * HEADDIM + col);
        y0.x += acc[nt][0]; y0.y += acc[nt][1];
        y1.x += acc[nt][2]; y1.y += acc[nt][3];
        *(float2*)(g_y + r0 * D_INNER + h * HEADDIM + col) = y0;
        *(float2*)(g_y + r1 * D_INNER + h * HEADDIM + col) = y1;
    }
}

// ---------------- gate + RMSNorm, emits fp16 hi plane directly ----------------
__global__ void __launch_bounds__(256) gate_norm_cvt_kernel(
    const float* __restrict__ nw, __half* __restrict__ yhi)
{
    const int row = blockIdx.x;
    const int tid = threadIdx.x;
    const float* zrow = g_zx + (size_t)row * D_IN_PROJ;
    const float* yrow = g_y  + (size_t)row * D_INNER;

    float g[16];
    float ss = 0.f;
#pragma unroll
    for (int i = 0; i < 4; ++i) {
        const int e = i * 1024 + tid * 4;
        const float4 yv = *(const float4*)(yrow + e);
        const float4 zv = *(const float4*)(zrow + e);
        float g0 = yv.x * (zv.x / (1.f + expf(-zv.x)));
        float g1 = yv.y * (zv.y / (1.f + expf(-zv.y)));
        float g2 = yv.z * (zv.z / (1.f + expf(-zv.z)));
        float g3 = yv.w * (zv.w / (1.f + expf(-zv.w)));
        g[i*4+0] = g0; g[i*4+1] = g1; g[i*4+2] = g2; g[i*4+3] = g3;
        ss += g0*g0 + g1*g1 + g2*g2 + g3*g3;
    }

    ss += __shfl_xor_sync(0xffffffffu, ss, 16);
    ss += __shfl_xor_sync(0xffffffffu, ss, 8);
    ss += __shfl_xor_sync(0xffffffffu, ss, 4);
    ss += __shfl_xor_sync(0xffffffffu, ss, 2);
    ss += __shfl_xor_sync(0xffffffffu, ss, 1);
    __shared__ float red[8];
    if ((tid & 31) == 0) red[tid >> 5] = ss;
    __syncthreads();
    float tot = 0.f;
#pragma unroll
    for (int w = 0; w < 8; ++w) tot += red[w];

    const float scale = rsqrtf(tot / (float)D_INNER + RMS_EPS);
#pragma unroll
    for (int i = 0; i < 4; ++i) {
        const int e = i * 1024 + tid * 4;
        const float v0 = g[i*4+0] * scale * nw[e+0];
        const float v1 = g[i*4+1] * scale * nw[e+1];
        const float v2 = g[i*4+2] * scale * nw[e+2];
        const float v3 = g[i*4+3] * scale * nw[e+3];
        __half2* hp = (__half2*)(yhi + (size_t)row * D_INNER + e);
        hp[0] = __halves2half2(__float2half_rn(v0), __float2half_rn(v1));
        hp[1] = __halves2half2(__float2half_rn(v2), __float2half_rn(v3));
    }
}

// ---------------- launch ----------------
extern "C" void kernel_launch(void* const* d_in, const int* in_sizes, int n_in,
                              void* d_out, int out_size)
{
    const float* x          = (const float*)d_in[0];
    const float* in_proj_w  = (const float*)d_in[3];
    const float* conv_w     = (const float*)d_in[4];
    const float* conv_b     = (const float*)d_in[5];
    const float* dt_bias    = (const float*)d_in[6];
    const float* A_log      = (const float*)d_in[7];
    const float* Dskip      = (const float*)d_in[8];
    const float* norm_w     = (const float*)d_in[9];
    const float* out_proj_w = (const float*)d_in[10];
    float* out = (float*)d_out;

    float *zx;
    __half *xc, *w1c, *yc, *w2c;
    cudaGetSymbolAddress((void**)&zx,  g_zx);
    cudaGetSymbolAddress((void**)&xc,  g_xc);
    cudaGetSymbolAddress((void**)&w1c, g_w1c);
    cudaGetSymbolAddress((void**)&yc,  g_yc);
    cudaGetSymbolAddress((void**)&w2c, g_w2c);

    cudaFuncSetAttribute(mma_gemm_f16x2,
                         cudaFuncAttributeMaxDynamicSharedMemorySize, GEMM_SMEM);
    cudaFuncSetAttribute(ssd_chunk_kernel,
                         cudaFuncAttributeMaxDynamicSharedMemorySize, SSD_SMEM);
    cudaFuncSetAttribute(ssd_correct_kernel,
                         cudaFuncAttributeMaxDynamicSharedMemorySize, K3_SMEM);

    // 0) convert: x -> hi plane; weights -> hi+lo planes
    {
        const int nx = NTOK * D_MODEL / 4;
        cvt_hi_kernel<<<(nx + 255) / 256, 256>>>(x, xc, nx);
        const int nw1 = D_IN_PROJ * D_MODEL / 4;
        cvt_f16x2_kernel<<<(nw1 + 255) / 256, 256>>>(in_proj_w, w1c, w1c + (size_t)D_IN_PROJ * D_MODEL, nw1);
        const int nw2 = D_MODEL * D_INNER / 4;
        cvt_f16x2_kernel<<<(nw2 + 255) / 256, 256>>>(out_proj_w, w2c, w2c + (size_t)D_MODEL * D_INNER, nw2);
    }

    // 1) in_proj: zx[4096, 8512] = x * W1^T
    {
        dim3 grid(NTOK / 128, (D_IN_PROJ + 127) / 128);
        mma_gemm_f16x2<<<grid, 256, GEMM_SMEM>>>(
            xc, w1c, w1c + (size_t)D_IN_PROJ * D_MODEL,
            zx, NTOK, D_IN_PROJ, D_MODEL);
    }
    // 2) conv + silu
    {
        dim3 grid(CONV_DIM / 256, TLEN / 32, BATCH);
        conv_silu_kernel<<<grid, 256>>>(conv_w, conv_b);
    }
    // 3) SSD chunked scan: intra-chunk (tensor) -> combine -> inter-chunk (tensor)
    {
        dim3 gridA(NHEADS, BATCH, SSEG);
        ssd_chunk_kernel<<<gridA, 256, SSD_SMEM>>>(dt_bias, A_log, Dskip);
        seg_combine_kernel<<<BATCH * NHEADS, 256>>>(A_log);
        dim3 gridC(NHEADS, BATCH, SSEG - 1);
        ssd_correct_kernel<<<gridC, 256, K3_SMEM>>>(dt_bias, A_log);
    }
    // 4) gate + RMSNorm + fp16 hi (fused)
    gate_norm_cvt_kernel<<<NTOK, 256>>>(norm_w, yc);

    // 5) out_proj: out[4096, 2048] = y * W2^T
    {
        dim3 grid(NTOK / 128, D_MODEL / 128);
        mma_gemm_f16x2<<<grid, 256, GEMM_SMEM>>>(
            yc, w2c, w2c + (size_t)D_MODEL * D_INNER,
            out, NTOK, D_MODEL, D_INNER);
    }
}

// round 14
// speedup vs baseline: 1.5073x; 1.1219x over previous
#include <cuda_runtime.h>
#include <cuda_fp16.h>
#include <math.h>
#include <stdint.h>

#define D_MODEL   2048
#define D_INNER   4096
#define D_STATE   128
#define HEADDIM   64
#define NHEADS    64
#define CONV_DIM  4352     /* D_INNER + 2*D_STATE */
#define D_IN_PROJ 8512     /* 2*D_INNER + 2*D_STATE + NHEADS */
#define BATCH     2
#define TLEN      2048
#define NTOK      (BATCH*TLEN)   /* 4096 */
#define RMS_EPS   1e-5f

#define SSEG 16
#define TSEG (TLEN / SSEG)       /* 128 = SSD chunk */

// ---------------- scratch (device globals; no allocs allowed) ----------------
__device__ float g_zx [(size_t)NTOK * D_IN_PROJ];
__device__ float g_xbc[(size_t)NTOK * CONV_DIM];
__device__ float g_y  [(size_t)NTOK * D_INNER];

__device__ __half g_xc [(size_t)NTOK * D_MODEL];
__device__ __half g_w1c[(size_t)2 * D_IN_PROJ * D_MODEL];
__device__ __half g_yc [(size_t)NTOK * D_INNER];
__device__ __half g_w2c[(size_t)2 * D_MODEL * D_INNER];

__device__ __forceinline__ uint32_t smem_to_u32(const void* p) {
    uint32_t a;
    asm("{ .reg .u64 t; cvta.to.shared.u64 t, %1; cvt.u32.u64 %0, t; }" : "=r"(a) : "l"(p));
    return a;
}
__device__ __forceinline__ float softplus1(float raw) {
    return (raw > 20.f) ? raw : log1pf(expf(raw));
}

// ---------------- fp32 -> fp16 hi plane only ----------------
__global__ void __launch_bounds__(256) cvt_hi_kernel(
    const float* __restrict__ src, __half* __restrict__ hi, int n4)
{
    const int i = blockIdx.x * 256 + threadIdx.x;
    if (i >= n4) return;
    const float4 v = ((const float4*)src)[i];
    __half2* hp = (__half2*)(hi + (size_t)i * 4);
    hp[0] = __halves2half2(__float2half_rn(v.x), __float2half_rn(v.y));
    hp[1] = __halves2half2(__float2half_rn(v.z), __float2half_rn(v.w));
}

// ---------------- fp32 -> (hi, lo) fp16 planes (weights) ----------------
__global__ void __launch_bounds__(256) cvt_f16x2_kernel(
    const float* __restrict__ src, __half* __restrict__ hi, __half* __restrict__ lo, int n4)
{
    const int i = blockIdx.x * 256 + threadIdx.x;
    if (i >= n4) return;
    const float4 v = ((const float4*)src)[i];
    __half h0 = __float2half_rn(v.x), h1 = __float2half_rn(v.y);
    __half h2 = __float2half_rn(v.z), h3 = __float2half_rn(v.w);
    __half l0 = __float2half_rn(v.x - __half2float(h0));
    __half l1 = __float2half_rn(v.y - __half2float(h1));
    __half l2 = __float2half_rn(v.z - __half2float(h2));
    __half l3 = __float2half_rn(v.w - __half2float(h3));
    __half2* hp = (__half2*)(hi + (size_t)i * 4);
    __half2* lp = (__half2*)(lo + (size_t)i * 4);
    hp[0] = __halves2half2(h0, h1); hp[1] = __halves2half2(h2, h3);
    lp[0] = __halves2half2(l0, l1); lp[1] = __halves2half2(l2, l3);
}

// ---------------- shared MMA helpers ----------------
__device__ __forceinline__ void mma16816(float* c, const uint32_t* a, const uint32_t* b) {
    asm volatile(
        "mma.sync.aligned.m16n8k16.row.col.f32.f16.f16.f32 "
        "{%0,%1,%2,%3}, {%4,%5,%6,%7}, {%8,%9}, {%0,%1,%2,%3};"
        : "+f"(c[0]), "+f"(c[1]), "+f"(c[2]), "+f"(c[3])
        : "r"(a[0]), "r"(a[1]), "r"(a[2]), "r"(a[3]), "r"(b[0]), "r"(b[1]));
}
__device__ __forceinline__ void ldsm4(uint32_t& r0, uint32_t& r1, uint32_t& r2, uint32_t& r3,
                                      uint32_t addr) {
    asm volatile("ldmatrix.sync.aligned.m8n8.x4.shared.b16 {%0,%1,%2,%3}, [%4];"
                 : "=r"(r0), "=r"(r1), "=r"(r2), "=r"(r3) : "r"(addr));
}

// ======== fp16 GEMM template: 128x128 tile, 3-stage pipeline, 2 CTAs/SM ========
// TERMS=2: acc += Ahi*Bhi + Ahi*Blo ; TERMS=1: acc += Ahi*Bhi only.
// C has leading dimension ldc (column-block writes supported).
#define PADH 40
#define PLANE_H (128 * PADH)
#define STAGE_B (3 * PLANE_H * 2)
#define GEMM_SMEM (3 * STAGE_B)

template<int TERMS>
__global__ void __launch_bounds__(256, 2) mma_gemm_tpl(
    const __half* __restrict__ Ahi,
    const __half* __restrict__ Bhi, const __half* __restrict__ Blo,
    float* __restrict__ C, int M, int Ncols, int K, int ldc)
{
    extern __shared__ __half sh[];
    const int tid  = threadIdx.x;
    const int wid  = tid >> 5;
    const int lane = tid & 31;
    const int g    = lane >> 2;
    const int tig  = lane & 3;
    const int bm   = blockIdx.x * 128;
    const int bn   = blockIdx.y * 128;
    const int wm   = (wid & 1) * 64;
    const int wn   = (wid >> 1) * 32;

    const uint32_t sbase = smem_to_u32(sh);

    const int a_r = lane & 15;
    const int a_c = (lane >> 4) * 8;
    const int b_r = (lane & 7) + ((lane >> 4) << 3);
    const int b_c = ((lane >> 3) & 1) * 8;

    float acc[4][4][4];
#pragma unroll
    for (int mt = 0; mt < 4; ++mt)
#pragma unroll
        for (int nt = 0; nt < 4; ++nt)
#pragma unroll
            for (int q = 0; q < 4; ++q) acc[mt][nt][q] = 0.f;

    const int NC = K >> 5;

    auto load_stage = [&](int s, int c) {
        const int kb = c * 32;
        const uint32_t stg = sbase + (uint32_t)s * STAGE_B;
#pragma unroll
        for (int i = 0; i < 2; ++i) {
            const int f   = tid + 256 * i;
            const int row = f >> 2;
            const int seg = (f & 3) * 8;
            const uint32_t doff = (uint32_t)(row * PADH + seg) * 2u;
            {
                const __half* p = Ahi + (size_t)(bm + row) * K + kb + seg;
                asm volatile("cp.async.cg.shared.global [%0], [%1], 16;"
                             :: "r"(stg + doff), "l"(p) : "memory");
            }
            {
                const int brow = bn + row;
                const int safe = (brow < Ncols) ? brow : 0;
                const uint32_t sz = (brow < Ncols) ? 16u : 0u;
                const __half* p  = Bhi + (size_t)safe * K + kb + seg;
                asm volatile("cp.async.cg.shared.global [%0], [%1], 16, %2;"
                             :: "r"(stg + (uint32_t)PLANE_H * 2u + doff), "l"(p), "r"(sz) : "memory");
                if (TERMS == 2) {
                    const __half* q2 = Blo + (size_t)safe * K + kb + seg;
                    asm volatile("cp.async.cg.shared.global [%0], [%1], 16, %2;"
                                 :: "r"(stg + (uint32_t)(2 * PLANE_H) * 2u + doff), "l"(q2), "r"(sz) : "memory");
                }
            }
        }
        asm volatile("cp.async.commit_group;" ::: "memory");
    };

    auto compute_stage = [&](int s) {
        const uint32_t stg = sbase + (uint32_t)s * STAGE_B;
        const uint32_t aHi = stg;
        const uint32_t bHi = stg + (uint32_t)PLANE_H * 2u;
        const uint32_t bLo = stg + (uint32_t)(2 * PLANE_H) * 2u;
#pragma unroll
        for (int ks = 0; ks < 2; ++ks) {
            const int k0 = ks * 16;
            uint32_t ah[4][4], bh[4][2], bl[4][2];
#pragma unroll
            for (int p = 0; p < 2; ++p) {
                const uint32_t off = (uint32_t)((wn + p * 16 + b_r) * PADH + k0 + b_c) * 2u;
                ldsm4(bh[2*p][0], bh[2*p][1], bh[2*p+1][0], bh[2*p+1][1], bHi + off);
                if (TERMS == 2)
                    ldsm4(bl[2*p][0], bl[2*p][1], bl[2*p+1][0], bl[2*p+1][1], bLo + off);
            }
#pragma unroll
            for (int mt = 0; mt < 4; ++mt) {
                const uint32_t off = (uint32_t)((wm + mt * 16 + a_r) * PADH + k0 + a_c) * 2u;
                ldsm4(ah[mt][0], ah[mt][1], ah[mt][2], ah[mt][3], aHi + off);
            }
#pragma unroll
            for (int mt = 0; mt < 4; ++mt)
#pragma unroll
                for (int nt = 0; nt < 4; ++nt)
                    mma16816(acc[mt][nt], ah[mt], bh[nt]);
            if (TERMS == 2) {
#pragma unroll
                for (int mt = 0; mt < 4; ++mt)
#pragma unroll
                    for (int nt = 0; nt < 4; ++nt)
                        mma16816(acc[mt][nt], ah[mt], bl[nt]);
            }
        }
    };

    load_stage(0, 0);
    load_stage(1, 1);
    for (int c = 0; c < NC; ++c) {
        if (c + 2 < NC) {
            asm volatile("cp.async.wait_group 1;" ::: "memory");
        } else {
            asm volatile("cp.async.wait_group 0;" ::: "memory");
        }
        __syncthreads();
        if (c + 2 < NC) load_stage((c + 2) % 3, c + 2);
        compute_stage(c % 3);
    }

#pragma unroll
    for (int mt = 0; mt < 4; ++mt) {
        const int row0 = bm + wm + mt * 16 + g;
#pragma unroll
        for (int nt = 0; nt < 4; ++nt) {
            const int col = bn + wn + nt * 8 + tig * 2;
            if (col < Ncols) {
                *(float2*)(C + (size_t)row0 * ldc + col)       = make_float2(acc[mt][nt][0], acc[mt][nt][1]);
                *(float2*)(C + (size_t)(row0 + 8) * ldc + col) = make_float2(acc[mt][nt][2], acc[mt][nt][3]);
            }
        }
    }
}

// ---------------- depthwise causal conv (width 4) + SiLU ----------------
__global__ void __launch_bounds__(256) conv_silu_kernel(
    const float* __restrict__ cw, const float* __restrict__ cb)
{
    const int c  = blockIdx.x * 256 + threadIdx.x;
    const int b  = blockIdx.z;
    const int t0 = blockIdx.y * 32;

    const float w0 = cw[c*4+0], w1 = cw[c*4+1], w2 = cw[c*4+2], w3 = cw[c*4+3];
    const float bias = cb[c];

    const float* base = g_zx + ((size_t)b * TLEN) * D_IN_PROJ + D_INNER + c;
    float* ob = g_xbc + ((size_t)b * TLEN) * CONV_DIM + c;

    float x0 = (t0 >= 3) ? base[(size_t)(t0-3) * D_IN_PROJ] : 0.f;
    float x1 = (t0 >= 2) ? base[(size_t)(t0-2) * D_IN_PROJ] : 0.f;
    float x2 = (t0 >= 1) ? base[(size_t)(t0-1) * D_IN_PROJ] : 0.f;

    for (int t = t0; t < t0 + 32; ++t) {
        const float x3 = base[(size_t)t * D_IN_PROJ];
        const float v  = bias + x0*w0 + x1*w1 + x2*w2 + x3*w3;
        ob[(size_t)t * CONV_DIM] = v / (1.f + expf(-v));
        x0 = x1; x1 = x2; x2 = x3;
    }
}

// ======================= fully-fused SSD scan =======================
// One block per (h, b); walks 16 chunks sequentially carrying state S[64][128]
// in shared fp32. Per chunk: Gcorr = C @ Sprev^T (inter-chunk), G = C @ B^T,
// Y = (L o G) @ X + ri*Gcorr + Dskip*x, S = P*S + Xw^T @ B (wj folded into B tile).
#define PADN 136
#define PADNF 132
#define OFF_CT  0
#define OFF_BT  17408
#define OFF_BT2 34816
#define OFF_L   52224
#define OFF_XT  69632      /* 64 x PADN */
#define OFF_SPH 78336      /* 64 x PADN */
#define SSD_FLT 87040      /* halves before float area */
// float area: Sf[64*PADNF]=8448, sdt 128, sda 128, scum 128, fw 4
#define SSD_SMEM (SSD_FLT * 2 + (8448 + 388 + 4) * 4)

__global__ void __launch_bounds__(256, 1) ssd_fused_kernel(
    const float* __restrict__ dt_bias, const float* __restrict__ A_log,
    const float* __restrict__ Dskip)
{
    extern __shared__ __half sh[];
    float* fb   = (float*)(sh + SSD_FLT);
    float* Sf   = fb;               // [64 * PADNF]
    float* sdt  = fb + 8448;        // [128]
    float* sda  = sdt + 128;
    float* scum = sda + 128;
    float* fw   = scum + 128;       // [4]

    const int h = blockIdx.x, b = blockIdx.y;
    const int tid = threadIdx.x;
    const int wid = tid >> 5;
    const int lane = tid & 31;
    const int g   = lane >> 2;
    const int tig = lane & 3;
    const int a_r = lane & 15;
    const int a_c = (lane >> 4) * 8;
    const int b_r = (lane & 7) + ((lane >> 4) << 3);
    const int b_c = ((lane >> 3) & 1) * 8;

    const float Acoef = -expf(A_log[h]);
    const float dtb   = dt_bias[h];
    const float dsk   = Dskip[h];

    const uint32_t sb   = smem_to_u32(sh);
    const uint32_t uCT  = sb + OFF_CT  * 2u;
    const uint32_t uBT  = sb + OFF_BT  * 2u;
    const uint32_t uBT2 = sb + OFF_BT2 * 2u;
    const uint32_t uXT  = sb + OFF_XT  * 2u;
    const uint32_t uSPH = sb + OFF_SPH * 2u;

    // init state
    for (int e = tid; e < 64 * PADNF; e += 256) Sf[e] = 0.f;
    __syncthreads();

    for (int s = 0; s < SSEG; ++s) {
        const int t0 = s * TSEG;
        const size_t rbase = (size_t)(b * TLEN + t0);

        // ---- phase 0a: dt, dA, prefix-scan of dt ----
        float vscan = 0.f;
        if (tid < 128) {
            const float raw = g_zx[(rbase + tid) * D_IN_PROJ + (D_INNER + CONV_DIM) + h] + dtb;
            const float dt  = softplus1(raw);
            sdt[tid] = dt;
            sda[tid] = expf(dt * Acoef);
            float v = dt;
#pragma unroll
            for (int o = 1; o < 32; o <<= 1) {
                const float t = __shfl_up_sync(0xffffffffu, v, o);
                if (lane >= o) v += t;
            }
            vscan = v;
            if (lane == 31) fw[wid] = v;
        }
        __syncthreads();
        if (tid < 128) {
            float off = 0.f;
            for (int w = 0; w < wid; ++w) off += fw[w];
            scum[tid] = off + vscan;
        }
        __syncthreads();

        const float cumTot = scum[127];
        const float P = expf(Acoef * cumTot);

        // ---- phase 0b: stage CT, BT, BT2 (wj-scaled), XT, L, SprevH ----
        {
            const int t  = tid >> 1;
            const int sg = (tid & 1) * 64;
            const float wj = sdt[t] * expf(Acoef * (cumTot - scum[t]));
            const float* row = g_xbc + (rbase + t) * CONV_DIM + D_INNER;
#pragma unroll
            for (int u = 0; u < 16; ++u) {
                const float4 bb = *(const float4*)(row + sg + 4 * u);
                __half2* bp = (__half2*)(sh + OFF_BT + t * PADN + sg + 4 * u);
                bp[0] = __floats2half2_rn(bb.x, bb.y);
                bp[1] = __floats2half2_rn(bb.z, bb.w);
                sh[OFF_BT2 + (sg + 4*u + 0) * PADN + t] = __float2half_rn(wj * bb.x);
                sh[OFF_BT2 + (sg + 4*u + 1) * PADN + t] = __float2half_rn(wj * bb.y);
                sh[OFF_BT2 + (sg + 4*u + 2) * PADN + t] = __float2half_rn(wj * bb.z);
                sh[OFF_BT2 + (sg + 4*u + 3) * PADN + t] = __float2half_rn(wj * bb.w);
                const float4 cc = *(const float4*)(row + D_STATE + sg + 4 * u);
                __half2* cp = (__half2*)(sh + OFF_CT + t * PADN + sg + 4 * u);
                cp[0] = __floats2half2_rn(cc.x, cc.y);
                cp[1] = __floats2half2_rn(cc.z, cc.w);
            }
        }
        if (tid < 128) {
            const int t = tid;
            const float* xrow = g_xbc + (rbase + t) * CONV_DIM + h * HEADDIM;
#pragma unroll
            for (int u = 0; u < 16; ++u) {
                const float4 xv = *(const float4*)(xrow + 4 * u);
                const int p = 4 * u;
                sh[OFF_XT + (p+0) * PADN + t] = __float2half_rn(xv.x);
                sh[OFF_XT + (p+1) * PADN + t] = __float2half_rn(xv.y);
                sh[OFF_XT + (p+2) * PADN + t] = __float2half_rn(xv.z);
                sh[OFF_XT + (p+3) * PADN + t] = __float2half_rn(xv.w);
            }
            // L column j = tid (validated serial build)
            const int j = tid;
            const float dtj = sdt[j];
            float val = 0.f;
            for (int i = 0; i < 128; ++i) {
                val = (i == j) ? dtj : sda[i] * val;
                sh[OFF_L + i * PADN + j] = __float2half_rn(val);
            }
        }
        if (s > 0) {
            for (int e = tid; e < 64 * 128; e += 256) {
                const int p = e >> 7, n = e & 127;
                sh[OFF_SPH + p * PADN + n] = __float2half_rn(Sf[p * PADNF + n]);
            }
        }
        __syncthreads();

        const int wm1 = wid * 16;
        const int i0  = wm1 + g;

        // ---- Gcorr = C @ Sprev^T  (M=128 i, N=64 p, K=128 n) ----
        float accc[8][4];
#pragma unroll
        for (int nt = 0; nt < 8; ++nt)
#pragma unroll
            for (int q = 0; q < 4; ++q) accc[nt][q] = 0.f;
        if (s > 0) {
#pragma unroll
            for (int ks = 0; ks < 8; ++ks) {
                const int k0 = ks * 16;
                uint32_t ah[4];
                ldsm4(ah[0], ah[1], ah[2], ah[3],
                      uCT + (uint32_t)((wm1 + a_r) * PADN + k0 + a_c) * 2u);
                uint32_t bh[8][2];
#pragma unroll
                for (int p4 = 0; p4 < 4; ++p4)
                    ldsm4(bh[2*p4][0], bh[2*p4][1], bh[2*p4+1][0], bh[2*p4+1][1],
                          uSPH + (uint32_t)((p4 * 16 + b_r) * PADN + k0 + b_c) * 2u);
#pragma unroll
                for (int nt = 0; nt < 8; ++nt)
                    mma16816(accc[nt], ah, bh[nt]);
            }
        }

        // ---- GEMM1: G = C @ B^T ----
        float acc1[16][4];
#pragma unroll
        for (int nt = 0; nt < 16; ++nt)
#pragma unroll
            for (int q = 0; q < 4; ++q) acc1[nt][q] = 0.f;
#pragma unroll
        for (int ks = 0; ks < 8; ++ks) {
            const int k0 = ks * 16;
            uint32_t ah[4];
            ldsm4(ah[0], ah[1], ah[2], ah[3],
                  uCT + (uint32_t)((wm1 + a_r) * PADN + k0 + a_c) * 2u);
            uint32_t bh[16][2];
#pragma unroll
            for (int p4 = 0; p4 < 8; ++p4)
                ldsm4(bh[2*p4][0], bh[2*p4][1], bh[2*p4+1][0], bh[2*p4+1][1],
                      uBT + (uint32_t)((p4 * 16 + b_r) * PADN + k0 + b_c) * 2u);
#pragma unroll
            for (int nt = 0; nt < 16; ++nt)
                mma16816(acc1[nt], ah, bh[nt]);
        }

        // ---- apply L, overwrite warp-private CT rows with Gp ----
#pragma unroll
        for (int nt = 0; nt < 16; ++nt) {
            const int col = nt * 8 + tig * 2;
            const float2 f0 = __half22float2(*(__half2*)(sh + OFF_L + i0 * PADN + col));
            const float2 f1 = __half22float2(*(__half2*)(sh + OFF_L + (i0 + 8) * PADN + col));
            *(__half2*)(sh + OFF_CT + i0 * PADN + col)       = __floats2half2_rn(acc1[nt][0] * f0.x, acc1[nt][1] * f0.y);
            *(__half2*)(sh + OFF_CT + (i0 + 8) * PADN + col) = __floats2half2_rn(acc1[nt][2] * f1.x, acc1[nt][3] * f1.y);
        }
        __syncwarp();

        // ---- GEMM2: Y_intra = Gp @ X^T ----
        float acc2[8][4];
#pragma unroll
        for (int nt = 0; nt < 8; ++nt)
#pragma unroll
            for (int q = 0; q < 4; ++q) acc2[nt][q] = 0.f;
#pragma unroll
        for (int ks = 0; ks < 8; ++ks) {
            const int k0 = ks * 16;
            uint32_t ah[4];
            ldsm4(ah[0], ah[1], ah[2], ah[3],
                  uCT + (uint32_t)((wm1 + a_r) * PADN + k0 + a_c) * 2u);
            uint32_t bh[8][2];
#pragma unroll
            for (int p4 = 0; p4 < 4; ++p4)
                ldsm4(bh[2*p4][0], bh[2*p4][1], bh[2*p4+1][0], bh[2*p4+1][1],
                      uXT + (uint32_t)((p4 * 16 + b_r) * PADN + k0 + b_c) * 2u);
#pragma unroll
            for (int nt = 0; nt < 8; ++nt)
                mma16816(acc2[nt], ah, bh[nt]);
        }

        // ---- Y epilogue: + ri*Gcorr + Dskip*x ----
        {
            const float ri0 = expf(Acoef * scum[i0]);
            const float ri1 = expf(Acoef * scum[i0 + 8]);
            const size_t r0 = rbase + i0;
            const size_t r1 = r0 + 8;
#pragma unroll
            for (int nt = 0; nt < 8; ++nt) {
                const int col = nt * 8 + tig * 2;
                const float2 x0 = *(const float2*)(g_xbc + r0 * CONV_DIM + h * HEADDIM + col);
                const float2 x1 = *(const float2*)(g_xbc + r1 * CONV_DIM + h * HEADDIM + col);
                *(float2*)(g_y + r0 * D_INNER + h * HEADDIM + col) =
                    make_float2(acc2[nt][0] + ri0 * accc[nt][0] + dsk * x0.x,
                                acc2[nt][1] + ri0 * accc[nt][1] + dsk * x0.y);
                *(float2*)(g_y + r1 * D_INNER + h * HEADDIM + col) =
                    make_float2(acc2[nt][2] + ri1 * accc[nt][2] + dsk * x1.x,
                                acc2[nt][3] + ri1 * accc[nt][3] + dsk * x1.y);
            }
        }

        // ---- GEMM3: Snew^T = Xw^T @ B  (A = XT, B = wj-scaled BT2) ----
        const int wm3 = (wid & 3) * 16;
        const int nb3 = (wid >> 2) * 64;
        float acc3[8][4];
#pragma unroll
        for (int nt = 0; nt < 8; ++nt)
#pragma unroll
            for (int q = 0; q < 4; ++q) acc3[nt][q] = 0.f;
#pragma unroll
        for (int ks = 0; ks < 8; ++ks) {
            const int k0 = ks * 16;
            uint32_t ah[4];
            ldsm4(ah[0], ah[1], ah[2], ah[3],
                  uXT + (uint32_t)((wm3 + a_r) * PADN + k0 + a_c) * 2u);
            uint32_t bh[8][2];
#pragma unroll
            for (int p4 = 0; p4 < 4; ++p4)
                ldsm4(bh[2*p4][0], bh[2*p4][1], bh[2*p4+1][0], bh[2*p4+1][1],
                      uBT2 + (uint32_t)((nb3 + p4 * 16 + b_r) * PADN + k0 + b_c) * 2u);
#pragma unroll
            for (int nt = 0; nt < 8; ++nt)
                mma16816(acc3[nt], ah, bh[nt]);
        }
        // state update: Sf = P*Sf + Snew (owner threads; no readers until barrier)
        {
            const int p0 = wm3 + g;
#pragma unroll
            for (int nt = 0; nt < 8; ++nt) {
                const int n = nb3 + nt * 8 + tig * 2;
                float* s0 = Sf + p0 * PADNF + n;
                float* s1 = Sf + (p0 + 8) * PADNF + n;
                s0[0] = P * s0[0] + acc3[nt][0];
                s0[1] = P * s0[1] + acc3[nt][1];
                s1[0] = P * s1[0] + acc3[nt][2];
                s1[1] = P * s1[1] + acc3[nt][3];
            }
        }
        __syncthreads();
    }
}

// ---------------- gate + RMSNorm, emits fp16 hi plane directly ----------------
__global__ void __launch_bounds__(256) gate_norm_cvt_kernel(
    const float* __restrict__ nw, __half* __restrict__ yhi)
{
    const int row = blockIdx.x;
    const int tid = threadIdx.x;
    const float* zrow = g_zx + (size_t)row * D_IN_PROJ;
    const float* yrow = g_y  + (size_t)row * D_INNER;

    float g[16];
    float ss = 0.f;
#pragma unroll
    for (int i = 0; i < 4; ++i) {
        const int e = i * 1024 + tid * 4;
        const float4 yv = *(const float4*)(yrow + e);
        const float4 zv = *(const float4*)(zrow + e);
        float g0 = yv.x * (zv.x / (1.f + expf(-zv.x)));
        float g1 = yv.y * (zv.y / (1.f + expf(-zv.y)));
        float g2 = yv.z * (zv.z / (1.f + expf(-zv.z)));
        float g3 = yv.w * (zv.w / (1.f + expf(-zv.w)));
        g[i*4+0] = g0; g[i*4+1] = g1; g[i*4+2] = g2; g[i*4+3] = g3;
        ss += g0*g0 + g1*g1 + g2*g2 + g3*g3;
    }

    ss += __shfl_xor_sync(0xffffffffu, ss, 16);
    ss += __shfl_xor_sync(0xffffffffu, ss, 8);
    ss += __shfl_xor_sync(0xffffffffu, ss, 4);
    ss += __shfl_xor_sync(0xffffffffu, ss, 2);
    ss += __shfl_xor_sync(0xffffffffu, ss, 1);
    __shared__ float red[8];
    if ((tid & 31) == 0) red[tid >> 5] = ss;
    __syncthreads();
    float tot = 0.f;
#pragma unroll
    for (int w = 0; w < 8; ++w) tot += red[w];

    const float scale = rsqrtf(tot / (float)D_INNER + RMS_EPS);
#pragma unroll
    for (int i = 0; i < 4; ++i) {
        const int e = i * 1024 + tid * 4;
        const float v0 = g[i*4+0] * scale * nw[e+0];
        const float v1 = g[i*4+1] * scale * nw[e+1];
        const float v2 = g[i*4+2] * scale * nw[e+2];
        const float v3 = g[i*4+3] * scale * nw[e+3];
        __half2* hp = (__half2*)(yhi + (size_t)row * D_INNER + e);
        hp[0] = __halves2half2(__float2half_rn(v0), __float2half_rn(v1));
        hp[1] = __halves2half2(__float2half_rn(v2), __float2half_rn(v3));
    }
}

// ---------------- launch ----------------
extern "C" void kernel_launch(void* const* d_in, const int* in_sizes, int n_in,
                              void* d_out, int out_size)
{
    const float* x          = (const float*)d_in[0];
    const float* in_proj_w  = (const float*)d_in[3];
    const float* conv_w     = (const float*)d_in[4];
    const float* conv_b     = (const float*)d_in[5];
    const float* dt_bias    = (const float*)d_in[6];
    const float* A_log      = (const float*)d_in[7];
    const float* Dskip      = (const float*)d_in[8];
    const float* norm_w     = (const float*)d_in[9];
    const float* out_proj_w = (const float*)d_in[10];
    float* out = (float*)d_out;

    float *zx;
    __half *xc, *w1c, *yc, *w2c;
    cudaGetSymbolAddress((void**)&zx,  g_zx);
    cudaGetSymbolAddress((void**)&xc,  g_xc);
    cudaGetSymbolAddress((void**)&w1c, g_w1c);
    cudaGetSymbolAddress((void**)&yc,  g_yc);
    cudaGetSymbolAddress((void**)&w2c, g_w2c);

    cudaFuncSetAttribute(mma_gemm_tpl<1>,
                         cudaFuncAttributeMaxDynamicSharedMemorySize, GEMM_SMEM);
    cudaFuncSetAttribute(mma_gemm_tpl<2>,
                         cudaFuncAttributeMaxDynamicSharedMemorySize, GEMM_SMEM);
    cudaFuncSetAttribute(ssd_fused_kernel,
                         cudaFuncAttributeMaxDynamicSharedMemorySize, SSD_SMEM);

    // 0) convert: x -> hi plane; weights -> hi+lo planes
    {
        const int nx = NTOK * D_MODEL / 4;
        cvt_hi_kernel<<<(nx + 255) / 256, 256>>>(x, xc, nx);
        const int nw1 = D_IN_PROJ * D_MODEL / 4;
        cvt_f16x2_kernel<<<(nw1 + 255) / 256, 256>>>(in_proj_w, w1c, w1c + (size_t)D_IN_PROJ * D_MODEL, nw1);
        const int nw2 = D_MODEL * D_INNER / 4;
        cvt_f16x2_kernel<<<(nw2 + 255) / 256, 256>>>(out_proj_w, w2c, w2c + (size_t)D_MODEL * D_INNER, nw2);
    }

    const __half* w1lo = w1c + (size_t)D_IN_PROJ * D_MODEL;

    // 1a) in_proj z-part (cols [0,4096)): single-term fp16
    {
        dim3 grid(NTOK / 128, D_INNER / 128);
        mma_gemm_tpl<1><<<grid, 256, GEMM_SMEM>>>(
            xc, w1c, (const __half*)nullptr,
            zx, NTOK, D_INNER, D_MODEL, D_IN_PROJ);
    }
    // 1b) in_proj rest (cols [4096,8512)): two-term fp16
    {
        const int ncols = D_IN_PROJ - D_INNER;   // 4416
        dim3 grid(NTOK / 128, (ncols + 127) / 128);
        mma_gemm_tpl<2><<<grid, 256, GEMM_SMEM>>>(
            xc,
            w1c  + (size_t)D_INNER * D_MODEL,
            w1lo + (size_t)D_INNER * D_MODEL,
            zx + D_INNER, NTOK, ncols, D_MODEL, D_IN_PROJ);
    }
    // 2) conv + silu
    {
        dim3 grid(CONV_DIM / 256, TLEN / 32, BATCH);
        conv_silu_kernel<<<grid, 256>>>(conv_w, conv_b);
    }
    // 3) fully-fused SSD scan
    {
        dim3 grid(NHEADS, BATCH);
        ssd_fused_kernel<<<grid, 256, SSD_SMEM>>>(dt_bias, A_log, Dskip);
    }
    // 4) gate + RMSNorm + fp16 hi (fused)
    gate_norm_cvt_kernel<<<NTOK, 256>>>(norm_w, yc);

    // 5) out_proj
    {
        dim3 grid(NTOK / 128, D_MODEL / 128);
        mma_gemm_tpl<2><<<grid, 256, GEMM_SMEM>>>(
            yc, w2c, w2c + (size_t)D_MODEL * D_INNER,
            out, NTOK, D_MODEL, D_INNER, D_MODEL);
    }
}

// round 15
// speedup vs baseline: 1.9390x; 1.2864x over previous
#include <cuda_runtime.h>
#include <cuda_fp16.h>
#include <math.h>
#include <stdint.h>

#define D_MODEL   2048
#define D_INNER   4096
#define D_STATE   128
#define HEADDIM   64
#define NHEADS    64
#define CONV_DIM  4352     /* D_INNER + 2*D_STATE */
#define D_IN_PROJ 8512     /* 2*D_INNER + 2*D_STATE + NHEADS */
#define BATCH     2
#define TLEN      2048
#define NTOK      (BATCH*TLEN)   /* 4096 */
#define RMS_EPS   1e-5f

#define SSEG 16
#define TSEG (TLEN / SSEG)       /* 128 = SSD chunk */

// ---------------- scratch (device globals; no allocs allowed) ----------------
__device__ float g_zx [(size_t)NTOK * D_IN_PROJ];
__device__ float g_xbc[(size_t)NTOK * CONV_DIM];
__device__ float g_y  [(size_t)NTOK * D_INNER];

__device__ __half g_xc [(size_t)NTOK * D_MODEL];
__device__ __half g_w1c[(size_t)2 * D_IN_PROJ * D_MODEL];
__device__ __half g_yc [(size_t)NTOK * D_INNER];
__device__ __half g_w2c[(size_t)D_MODEL * D_INNER];

__device__ __forceinline__ uint32_t smem_to_u32(const void* p) {
    uint32_t a;
    asm("{ .reg .u64 t; cvta.to.shared.u64 t, %1; cvt.u32.u64 %0, t; }" : "=r"(a) : "l"(p));
    return a;
}
__device__ __forceinline__ float softplus1(float raw) {
    return (raw > 20.f) ? raw : log1pf(expf(raw));
}

// ---------------- fp32 -> fp16 hi plane only ----------------
__global__ void __launch_bounds__(256) cvt_hi_kernel(
    const float* __restrict__ src, __half* __restrict__ hi, int n4)
{
    const int i = blockIdx.x * 256 + threadIdx.x;
    if (i >= n4) return;
    const float4 v = ((const float4*)src)[i];
    __half2* hp = (__half2*)(hi + (size_t)i * 4);
    hp[0] = __halves2half2(__float2half_rn(v.x), __float2half_rn(v.y));
    hp[1] = __halves2half2(__float2half_rn(v.z), __float2half_rn(v.w));
}

// ---------------- fp32 -> (hi, lo) fp16 planes (weights) ----------------
__global__ void __launch_bounds__(256) cvt_f16x2_kernel(
    const float* __restrict__ src, __half* __restrict__ hi, __half* __restrict__ lo, int n4)
{
    const int i = blockIdx.x * 256 + threadIdx.x;
    if (i >= n4) return;
    const float4 v = ((const float4*)src)[i];
    __half h0 = __float2half_rn(v.x), h1 = __float2half_rn(v.y);
    __half h2 = __float2half_rn(v.z), h3 = __float2half_rn(v.w);
    __half l0 = __float2half_rn(v.x - __half2float(h0));
    __half l1 = __float2half_rn(v.y - __half2float(h1));
    __half l2 = __float2half_rn(v.z - __half2float(h2));
    __half l3 = __float2half_rn(v.w - __half2float(h3));
    __half2* hp = (__half2*)(hi + (size_t)i * 4);
    __half2* lp = (__half2*)(lo + (size_t)i * 4);
    hp[0] = __halves2half2(h0, h1); hp[1] = __halves2half2(h2, h3);
    lp[0] = __halves2half2(l0, l1); lp[1] = __halves2half2(l2, l3);
}

// ---------------- shared MMA helpers ----------------
__device__ __forceinline__ void mma16816(float* c, const uint32_t* a, const uint32_t* b) {
    asm volatile(
        "mma.sync.aligned.m16n8k16.row.col.f32.f16.f16.f32 "
        "{%0,%1,%2,%3}, {%4,%5,%6,%7}, {%8,%9}, {%0,%1,%2,%3};"
        : "+f"(c[0]), "+f"(c[1]), "+f"(c[2]), "+f"(c[3])
        : "r"(a[0]), "r"(a[1]), "r"(a[2]), "r"(a[3]), "r"(b[0]), "r"(b[1]));
}
__device__ __forceinline__ void ldsm4(uint32_t& r0, uint32_t& r1, uint32_t& r2, uint32_t& r3,
                                      uint32_t addr) {
    asm volatile("ldmatrix.sync.aligned.m8n8.x4.shared.b16 {%0,%1,%2,%3}, [%4];"
                 : "=r"(r0), "=r"(r1), "=r"(r2), "=r"(r3) : "r"(addr));
}

// ======== fp16 GEMM template: 128x128 tile, 3-stage pipeline, 2 CTAs/SM ========
#define PADH 40
#define PLANE_H (128 * PADH)
#define STAGE_B (3 * PLANE_H * 2)
#define GEMM_SMEM (3 * STAGE_B)

template<int TERMS>
__global__ void __launch_bounds__(256, 2) mma_gemm_tpl(
    const __half* __restrict__ Ahi,
    const __half* __restrict__ Bhi, const __half* __restrict__ Blo,
    float* __restrict__ C, int M, int Ncols, int K, int ldc)
{
    extern __shared__ __half sh[];
    const int tid  = threadIdx.x;
    const int wid  = tid >> 5;
    const int lane = tid & 31;
    const int g    = lane >> 2;
    const int tig  = lane & 3;
    const int bm   = blockIdx.x * 128;
    const int bn   = blockIdx.y * 128;
    const int wm   = (wid & 1) * 64;
    const int wn   = (wid >> 1) * 32;

    const uint32_t sbase = smem_to_u32(sh);

    const int a_r = lane & 15;
    const int a_c = (lane >> 4) * 8;
    const int b_r = (lane & 7) + ((lane >> 4) << 3);
    const int b_c = ((lane >> 3) & 1) * 8;

    float acc[4][4][4];
#pragma unroll
    for (int mt = 0; mt < 4; ++mt)
#pragma unroll
        for (int nt = 0; nt < 4; ++nt)
#pragma unroll
            for (int q = 0; q < 4; ++q) acc[mt][nt][q] = 0.f;

    const int NC = K >> 5;

    auto load_stage = [&](int s, int c) {
        const int kb = c * 32;
        const uint32_t stg = sbase + (uint32_t)s * STAGE_B;
#pragma unroll
        for (int i = 0; i < 2; ++i) {
            const int f   = tid + 256 * i;
            const int row = f >> 2;
            const int seg = (f & 3) * 8;
            const uint32_t doff = (uint32_t)(row * PADH + seg) * 2u;
            {
                const __half* p = Ahi + (size_t)(bm + row) * K + kb + seg;
                asm volatile("cp.async.cg.shared.global [%0], [%1], 16;"
                             :: "r"(stg + doff), "l"(p) : "memory");
            }
            {
                const int brow = bn + row;
                const int safe = (brow < Ncols) ? brow : 0;
                const uint32_t sz = (brow < Ncols) ? 16u : 0u;
                const __half* p  = Bhi + (size_t)safe * K + kb + seg;
                asm volatile("cp.async.cg.shared.global [%0], [%1], 16, %2;"
                             :: "r"(stg + (uint32_t)PLANE_H * 2u + doff), "l"(p), "r"(sz) : "memory");
                if (TERMS == 2) {
                    const __half* q2 = Blo + (size_t)safe * K + kb + seg;
                    asm volatile("cp.async.cg.shared.global [%0], [%1], 16, %2;"
                                 :: "r"(stg + (uint32_t)(2 * PLANE_H) * 2u + doff), "l"(q2), "r"(sz) : "memory");
                }
            }
        }
        asm volatile("cp.async.commit_group;" ::: "memory");
    };

    auto compute_stage = [&](int s) {
        const uint32_t stg = sbase + (uint32_t)s * STAGE_B;
        const uint32_t aHi = stg;
        const uint32_t bHi = stg + (uint32_t)PLANE_H * 2u;
        const uint32_t bLo = stg + (uint32_t)(2 * PLANE_H) * 2u;
#pragma unroll
        for (int ks = 0; ks < 2; ++ks) {
            const int k0 = ks * 16;
            uint32_t ah[4][4], bh[4][2], bl[4][2];
#pragma unroll
            for (int p = 0; p < 2; ++p) {
                const uint32_t off = (uint32_t)((wn + p * 16 + b_r) * PADH + k0 + b_c) * 2u;
                ldsm4(bh[2*p][0], bh[2*p][1], bh[2*p+1][0], bh[2*p+1][1], bHi + off);
                if (TERMS == 2)
                    ldsm4(bl[2*p][0], bl[2*p][1], bl[2*p+1][0], bl[2*p+1][1], bLo + off);
            }
#pragma unroll
            for (int mt = 0; mt < 4; ++mt) {
                const uint32_t off = (uint32_t)((wm + mt * 16 + a_r) * PADH + k0 + a_c) * 2u;
                ldsm4(ah[mt][0], ah[mt][1], ah[mt][2], ah[mt][3], aHi + off);
            }
#pragma unroll
            for (int mt = 0; mt < 4; ++mt)
#pragma unroll
                for (int nt = 0; nt < 4; ++nt)
                    mma16816(acc[mt][nt], ah[mt], bh[nt]);
            if (TERMS == 2) {
#pragma unroll
                for (int mt = 0; mt < 4; ++mt)
#pragma unroll
                    for (int nt = 0; nt < 4; ++nt)
                        mma16816(acc[mt][nt], ah[mt], bl[nt]);
            }
        }
    };

    load_stage(0, 0);
    load_stage(1, 1);
    for (int c = 0; c < NC; ++c) {
        if (c + 2 < NC) {
            asm volatile("cp.async.wait_group 1;" ::: "memory");
        } else {
            asm volatile("cp.async.wait_group 0;" ::: "memory");
        }
        __syncthreads();
        if (c + 2 < NC) load_stage((c + 2) % 3, c + 2);
        compute_stage(c % 3);
    }

#pragma unroll
    for (int mt = 0; mt < 4; ++mt) {
        const int row0 = bm + wm + mt * 16 + g;
#pragma unroll
        for (int nt = 0; nt < 4; ++nt) {
            const int col = bn + wn + nt * 8 + tig * 2;
            if (col < Ncols) {
                *(float2*)(C + (size_t)row0 * ldc + col)       = make_float2(acc[mt][nt][0], acc[mt][nt][1]);
                *(float2*)(C + (size_t)(row0 + 8) * ldc + col) = make_float2(acc[mt][nt][2], acc[mt][nt][3]);
            }
        }
    }
}

// ---------------- depthwise causal conv (width 4) + SiLU ----------------
__global__ void __launch_bounds__(256) conv_silu_kernel(
    const float* __restrict__ cw, const float* __restrict__ cb)
{
    const int c  = blockIdx.x * 256 + threadIdx.x;
    const int b  = blockIdx.z;
    const int t0 = blockIdx.y * 32;

    const float w0 = cw[c*4+0], w1 = cw[c*4+1], w2 = cw[c*4+2], w3 = cw[c*4+3];
    const float bias = cb[c];

    const float* base = g_zx + ((size_t)b * TLEN) * D_IN_PROJ + D_INNER + c;
    float* ob = g_xbc + ((size_t)b * TLEN) * CONV_DIM + c;

    float x0 = (t0 >= 3) ? base[(size_t)(t0-3) * D_IN_PROJ] : 0.f;
    float x1 = (t0 >= 2) ? base[(size_t)(t0-2) * D_IN_PROJ] : 0.f;
    float x2 = (t0 >= 1) ? base[(size_t)(t0-1) * D_IN_PROJ] : 0.f;

    for (int t = t0; t < t0 + 32; ++t) {
        const float x3 = base[(size_t)t * D_IN_PROJ];
        const float v  = bias + x0*w0 + x1*w1 + x2*w2 + x3*w3;
        ob[(size_t)t * CONV_DIM] = v / (1.f + expf(-v));
        x0 = x1; x1 = x2; x2 = x3;
    }
}

// ======================= fully-fused SSD scan (validated R14) =======================
#define PADN 136
#define PADNF 132
#define OFF_CT  0
#define OFF_BT  17408
#define OFF_BT2 34816
#define OFF_L   52224
#define OFF_XT  69632
#define OFF_SPH 78336
#define SSD_FLT 87040
#define SSD_SMEM (SSD_FLT * 2 + (8448 + 388 + 4) * 4)

__global__ void __launch_bounds__(256, 1) ssd_fused_kernel(
    const float* __restrict__ dt_bias, const float* __restrict__ A_log,
    const float* __restrict__ Dskip)
{
    extern __shared__ __half sh[];
    float* fb   = (float*)(sh + SSD_FLT);
    float* Sf   = fb;
    float* sdt  = fb + 8448;
    float* sda  = sdt + 128;
    float* scum = sda + 128;
    float* fw   = scum + 128;

    const int h = blockIdx.x, b = blockIdx.y;
    const int tid = threadIdx.x;
    const int wid = tid >> 5;
    const int lane = tid & 31;
    const int g   = lane >> 2;
    const int tig = lane & 3;
    const int a_r = lane & 15;
    const int a_c = (lane >> 4) * 8;
    const int b_r = (lane & 7) + ((lane >> 4) << 3);
    const int b_c = ((lane >> 3) & 1) * 8;

    const float Acoef = -expf(A_log[h]);
    const float dtb   = dt_bias[h];
    const float dsk   = Dskip[h];

    const uint32_t sb   = smem_to_u32(sh);
    const uint32_t uCT  = sb + OFF_CT  * 2u;
    const uint32_t uBT  = sb + OFF_BT  * 2u;
    const uint32_t uBT2 = sb + OFF_BT2 * 2u;
    const uint32_t uXT  = sb + OFF_XT  * 2u;
    const uint32_t uSPH = sb + OFF_SPH * 2u;

    for (int e = tid; e < 64 * PADNF; e += 256) Sf[e] = 0.f;
    __syncthreads();

    for (int s = 0; s < SSEG; ++s) {
        const int t0 = s * TSEG;
        const size_t rbase = (size_t)(b * TLEN + t0);

        float vscan = 0.f;
        if (tid < 128) {
            const float raw = g_zx[(rbase + tid) * D_IN_PROJ + (D_INNER + CONV_DIM) + h] + dtb;
            const float dt  = softplus1(raw);
            sdt[tid] = dt;
            sda[tid] = expf(dt * Acoef);
            float v = dt;
#pragma unroll
            for (int o = 1; o < 32; o <<= 1) {
                const float t = __shfl_up_sync(0xffffffffu, v, o);
                if (lane >= o) v += t;
            }
            vscan = v;
            if (lane == 31) fw[wid] = v;
        }
        __syncthreads();
        if (tid < 128) {
            float off = 0.f;
            for (int w = 0; w < wid; ++w) off += fw[w];
            scum[tid] = off + vscan;
        }
        __syncthreads();

        const float cumTot = scum[127];
        const float P = expf(Acoef * cumTot);

        {
            const int t  = tid >> 1;
            const int sg = (tid & 1) * 64;
            const float wj = sdt[t] * expf(Acoef * (cumTot - scum[t]));
            const float* row = g_xbc + (rbase + t) * CONV_DIM + D_INNER;
#pragma unroll
            for (int u = 0; u < 16; ++u) {
                const float4 bb = *(const float4*)(row + sg + 4 * u);
                __half2* bp = (__half2*)(sh + OFF_BT + t * PADN + sg + 4 * u);
                bp[0] = __floats2half2_rn(bb.x, bb.y);
                bp[1] = __floats2half2_rn(bb.z, bb.w);
                sh[OFF_BT2 + (sg + 4*u + 0) * PADN + t] = __float2half_rn(wj * bb.x);
                sh[OFF_BT2 + (sg + 4*u + 1) * PADN + t] = __float2half_rn(wj * bb.y);
                sh[OFF_BT2 + (sg + 4*u + 2) * PADN + t] = __float2half_rn(wj * bb.z);
                sh[OFF_BT2 + (sg + 4*u + 3) * PADN + t] = __float2half_rn(wj * bb.w);
                const float4 cc = *(const float4*)(row + D_STATE + sg + 4 * u);
                __half2* cp = (__half2*)(sh + OFF_CT + t * PADN + sg + 4 * u);
                cp[0] = __floats2half2_rn(cc.x, cc.y);
                cp[1] = __floats2half2_rn(cc.z, cc.w);
            }
        }
        if (tid < 128) {
            const int t = tid;
            const float* xrow = g_xbc + (rbase + t) * CONV_DIM + h * HEADDIM;
#pragma unroll
            for (int u = 0; u < 16; ++u) {
                const float4 xv = *(const float4*)(xrow + 4 * u);
                const int p = 4 * u;
                sh[OFF_XT + (p+0) * PADN + t] = __float2half_rn(xv.x);
                sh[OFF_XT + (p+1) * PADN + t] = __float2half_rn(xv.y);
                sh[OFF_XT + (p+2) * PADN + t] = __float2half_rn(xv.z);
                sh[OFF_XT + (p+3) * PADN + t] = __float2half_rn(xv.w);
            }
            const int j = tid;
            const float dtj = sdt[j];
            float val = 0.f;
            for (int i = 0; i < 128; ++i) {
                val = (i == j) ? dtj : sda[i] * val;
                sh[OFF_L + i * PADN + j] = __float2half_rn(val);
            }
        }
        if (s > 0) {
            for (int e = tid; e < 64 * 128; e += 256) {
                const int p = e >> 7, n = e & 127;
                sh[OFF_SPH + p * PADN + n] = __float2half_rn(Sf[p * PADNF + n]);
            }
        }
        __syncthreads();

        const int wm1 = wid * 16;
        const int i0  = wm1 + g;

        float accc[8][4];
#pragma unroll
        for (int nt = 0; nt < 8; ++nt)
#pragma unroll
            for (int q = 0; q < 4; ++q) accc[nt][q] = 0.f;
        if (s > 0) {
#pragma unroll
            for (int ks = 0; ks < 8; ++ks) {
                const int k0 = ks * 16;
                uint32_t ah[4];
                ldsm4(ah[0], ah[1], ah[2], ah[3],
                      uCT + (uint32_t)((wm1 + a_r) * PADN + k0 + a_c) * 2u);
                uint32_t bh[8][2];
#pragma unroll
                for (int p4 = 0; p4 < 4; ++p4)
                    ldsm4(bh[2*p4][0], bh[2*p4][1], bh[2*p4+1][0], bh[2*p4+1][1],
                          uSPH + (uint32_t)((p4 * 16 + b_r) * PADN + k0 + b_c) * 2u);
#pragma unroll
                for (int nt = 0; nt < 8; ++nt)
                    mma16816(accc[nt], ah, bh[nt]);
            }
        }

        float acc1[16][4];
#pragma unroll
        for (int nt = 0; nt < 16; ++nt)
#pragma unroll
            for (int q = 0; q < 4; ++q) acc1[nt][q] = 0.f;
#pragma unroll
        for (int ks = 0; ks < 8; ++ks) {
            const int k0 = ks * 16;
            uint32_t ah[4];
            ldsm4(ah[0], ah[1], ah[2], ah[3],
                  uCT + (uint32_t)((wm1 + a_r) * PADN + k0 + a_c) * 2u);
            uint32_t bh[16][2];
#pragma unroll
            for (int p4 = 0; p4 < 8; ++p4)
                ldsm4(bh[2*p4][0], bh[2*p4][1], bh[2*p4+1][0], bh[2*p4+1][1],
                      uBT + (uint32_t)((p4 * 16 + b_r) * PADN + k0 + b_c) * 2u);
#pragma unroll
            for (int nt = 0; nt < 16; ++nt)
                mma16816(acc1[nt], ah, bh[nt]);
        }

#pragma unroll
        for (int nt = 0; nt < 16; ++nt) {
            const int col = nt * 8 + tig * 2;
            const float2 f0 = __half22float2(*(__half2*)(sh + OFF_L + i0 * PADN + col));
            const float2 f1 = __half22float2(*(__half2*)(sh + OFF_L + (i0 + 8) * PADN + col));
            *(__half2*)(sh + OFF_CT + i0 * PADN + col)       = __floats2half2_rn(acc1[nt][0] * f0.x, acc1[nt][1] * f0.y);
            *(__half2*)(sh + OFF_CT + (i0 + 8) * PADN + col) = __floats2half2_rn(acc1[nt][2] * f1.x, acc1[nt][3] * f1.y);
        }
        __syncwarp();

        float acc2[8][4];
#pragma unroll
        for (int nt = 0; nt < 8; ++nt)
#pragma unroll
            for (int q = 0; q < 4; ++q) acc2[nt][q] = 0.f;
#pragma unroll
        for (int ks = 0; ks < 8; ++ks) {
            const int k0 = ks * 16;
            uint32_t ah[4];
            ldsm4(ah[0], ah[1], ah[2], ah[3],
                  uCT + (uint32_t)((wm1 + a_r) * PADN + k0 + a_c) * 2u);
            uint32_t bh[8][2];
#pragma unroll
            for (int p4 = 0; p4 < 4; ++p4)
                ldsm4(bh[2*p4][0], bh[2*p4][1], bh[2*p4+1][0], bh[2*p4+1][1],
                      uXT + (uint32_t)((p4 * 16 + b_r) * PADN + k0 + b_c) * 2u);
#pragma unroll
            for (int nt = 0; nt < 8; ++nt)
                mma16816(acc2[nt], ah, bh[nt]);
        }

        {
            const float ri0 = expf(Acoef * scum[i0]);
            const float ri1 = expf(Acoef * scum[i0 + 8]);
            const size_t r0 = rbase + i0;
            const size_t r1 = r0 + 8;
#pragma unroll
            for (int nt = 0; nt < 8; ++nt) {
                const int col = nt * 8 + tig * 2;
                const float2 x0 = *(const float2*)(g_xbc + r0 * CONV_DIM + h * HEADDIM + col);
                const float2 x1 = *(const float2*)(g_xbc + r1 * CONV_DIM + h * HEADDIM + col);
                *(float2*)(g_y + r0 * D_INNER + h * HEADDIM + col) =
                    make_float2(acc2[nt][0] + ri0 * accc[nt][0] + dsk * x0.x,
                                acc2[nt][1] + ri0 * accc[nt][1] + dsk * x0.y);
                *(float2*)(g_y + r1 * D_INNER + h * HEADDIM + col) =
                    make_float2(acc2[nt][2] + ri1 * accc[nt][2] + dsk * x1.x,
                                acc2[nt][3] + ri1 * accc[nt][3] + dsk * x1.y);
            }
        }

        const int wm3 = (wid & 3) * 16;
        const int nb3 = (wid >> 2) * 64;
        float acc3[8][4];
#pragma unroll
        for (int nt = 0; nt < 8; ++nt)
#pragma unroll
            for (int q = 0; q < 4; ++q) acc3[nt][q] = 0.f;
#pragma unroll
        for (int ks = 0; ks < 8; ++ks) {
            const int k0 = ks * 16;
            uint32_t ah[4];
            ldsm4(ah[0], ah[1], ah[2], ah[3],
                  uXT + (uint32_t)((wm3 + a_r) * PADN + k0 + a_c) * 2u);
            uint32_t bh[8][2];
#pragma unroll
            for (int p4 = 0; p4 < 4; ++p4)
                ldsm4(bh[2*p4][0], bh[2*p4][1], bh[2*p4+1][0], bh[2*p4+1][1],
                      uBT2 + (uint32_t)((nb3 + p4 * 16 + b_r) * PADN + k0 + b_c) * 2u);
#pragma unroll
            for (int nt = 0; nt < 8; ++nt)
                mma16816(acc3[nt], ah, bh[nt]);
        }
        {
            const int p0 = wm3 + g;
#pragma unroll
            for (int nt = 0; nt < 8; ++nt) {
                const int n = nb3 + nt * 8 + tig * 2;
                float* s0 = Sf + p0 * PADNF + n;
                float* s1 = Sf + (p0 + 8) * PADNF + n;
                s0[0] = P * s0[0] + acc3[nt][0];
                s0[1] = P * s0[1] + acc3[nt][1];
                s1[0] = P * s1[0] + acc3[nt][2];
                s1[1] = P * s1[1] + acc3[nt][3];
            }
        }
        __syncthreads();
    }
}

// ---------------- gate + RMSNorm, emits fp16 hi plane directly ----------------
__global__ void __launch_bounds__(256) gate_norm_cvt_kernel(
    const float* __restrict__ nw, __half* __restrict__ yhi)
{
    const int row = blockIdx.x;
    const int tid = threadIdx.x;
    const float* zrow = g_zx + (size_t)row * D_IN_PROJ;
    const float* yrow = g_y  + (size_t)row * D_INNER;

    float g[16];
    float ss = 0.f;
#pragma unroll
    for (int i = 0; i < 4; ++i) {
        const int e = i * 1024 + tid * 4;
        const float4 yv = *(const float4*)(yrow + e);
        const float4 zv = *(const float4*)(zrow + e);
        float g0 = yv.x * (zv.x / (1.f + expf(-zv.x)));
        float g1 = yv.y * (zv.y / (1.f + expf(-zv.y)));
        float g2 = yv.z * (zv.z / (1.f + expf(-zv.z)));
        float g3 = yv.w * (zv.w / (1.f + expf(-zv.w)));
        g[i*4+0] = g0; g[i*4+1] = g1; g[i*4+2] = g2; g[i*4+3] = g3;
        ss += g0*g0 + g1*g1 + g2*g2 + g3*g3;
    }

    ss += __shfl_xor_sync(0xffffffffu, ss, 16);
    ss += __shfl_xor_sync(0xffffffffu, ss, 8);
    ss += __shfl_xor_sync(0xffffffffu, ss, 4);
    ss += __shfl_xor_sync(0xffffffffu, ss, 2);
    ss += __shfl_xor_sync(0xffffffffu, ss, 1);
    __shared__ float red[8];
    if ((tid & 31) == 0) red[tid >> 5] = ss;
    __syncthreads();
    float tot = 0.f;
#pragma unroll
    for (int w = 0; w < 8; ++w) tot += red[w];

    const float scale = rsqrtf(tot / (float)D_INNER + RMS_EPS);
#pragma unroll
    for (int i = 0; i < 4; ++i) {
        const int e = i * 1024 + tid * 4;
        const float v0 = g[i*4+0] * scale * nw[e+0];
        const float v1 = g[i*4+1] * scale * nw[e+1];
        const float v2 = g[i*4+2] * scale * nw[e+2];
        const float v3 = g[i*4+3] * scale * nw[e+3];
        __half2* hp = (__half2*)(yhi + (size_t)row * D_INNER + e);
        hp[0] = __halves2half2(__float2half_rn(v0), __float2half_rn(v1));
        hp[1] = __halves2half2(__float2half_rn(v2), __float2half_rn(v3));
    }
}

// ---------------- launch ----------------
extern "C" void kernel_launch(void* const* d_in, const int* in_sizes, int n_in,
                              void* d_out, int out_size)
{
    const float* x          = (const float*)d_in[0];
    const float* in_proj_w  = (const float*)d_in[3];
    const float* conv_w     = (const float*)d_in[4];
    const float* conv_b     = (const float*)d_in[5];
    const float* dt_bias    = (const float*)d_in[6];
    const float* A_log      = (const float*)d_in[7];
    const float* Dskip      = (const float*)d_in[8];
    const float* norm_w     = (const float*)d_in[9];
    const float* out_proj_w = (const float*)d_in[10];
    float* out = (float*)d_out;

    float *zx;
    __half *xc, *w1c, *yc, *w2c;
    cudaGetSymbolAddress((void**)&zx,  g_zx);
    cudaGetSymbolAddress((void**)&xc,  g_xc);
    cudaGetSymbolAddress((void**)&w1c, g_w1c);
    cudaGetSymbolAddress((void**)&yc,  g_yc);
    cudaGetSymbolAddress((void**)&w2c, g_w2c);

    cudaFuncSetAttribute(mma_gemm_tpl<1>,
                         cudaFuncAttributeMaxDynamicSharedMemorySize, GEMM_SMEM);
    cudaFuncSetAttribute(mma_gemm_tpl<2>,
                         cudaFuncAttributeMaxDynamicSharedMemorySize, GEMM_SMEM);
    cudaFuncSetAttribute(ssd_fused_kernel,
                         cudaFuncAttributeMaxDynamicSharedMemorySize, SSD_SMEM);

    // 0) convert: x, w2 -> hi plane only; w1 -> hi+lo planes (lo used only for dt tile)
    {
        const int nx = NTOK * D_MODEL / 4;
        cvt_hi_kernel<<<(nx + 255) / 256, 256>>>(x, xc, nx);
        const int nw1 = D_IN_PROJ * D_MODEL / 4;
        cvt_f16x2_kernel<<<(nw1 + 255) / 256, 256>>>(in_proj_w, w1c, w1c + (size_t)D_IN_PROJ * D_MODEL, nw1);
        const int nw2 = D_MODEL * D_INNER / 4;
        cvt_hi_kernel<<<(nw2 + 255) / 256, 256>>>(out_proj_w, w2c, nw2);
    }

    const __half* w1lo = w1c + (size_t)D_IN_PROJ * D_MODEL;

    // 1a) in_proj cols [0, 8448) (z + xBC): single-term fp16
    {
        const int ncols = D_INNER + CONV_DIM;   // 8448 = 66 * 128
        dim3 grid(NTOK / 128, ncols / 128);
        mma_gemm_tpl<1><<<grid, 256, GEMM_SMEM>>>(
            xc, w1c, (const __half*)nullptr,
            zx, NTOK, ncols, D_MODEL, D_IN_PROJ);
    }
    // 1b) in_proj dt cols [8448, 8512): two-term fp16 (accuracy-critical: feeds exp chains)
    {
        const int c0 = D_INNER + CONV_DIM;      // 8448
        dim3 grid(NTOK / 128, 1);
        mma_gemm_tpl<2><<<grid, 256, GEMM_SMEM>>>(
            xc,
            w1c  + (size_t)c0 * D_MODEL,
            w1lo + (size_t)c0 * D_MODEL,
            zx + c0, NTOK, D_IN_PROJ - c0, D_MODEL, D_IN_PROJ);
    }
    // 2) conv + silu
    {
        dim3 grid(CONV_DIM / 256, TLEN / 32, BATCH);
        conv_silu_kernel<<<grid, 256>>>(conv_w, conv_b);
    }
    // 3) fully-fused SSD scan
    {
        dim3 grid(NHEADS, BATCH);
        ssd_fused_kernel<<<grid, 256, SSD_SMEM>>>(dt_bias, A_log, Dskip);
    }
    // 4) gate + RMSNorm + fp16 hi (fused)
    gate_norm_cvt_kernel<<<NTOK, 256>>>(norm_w, yc);

    // 5) out_proj: single-term fp16
    {
        dim3 grid(NTOK / 128, D_MODEL / 128);
        mma_gemm_tpl<1><<<grid, 256, GEMM_SMEM>>>(
            yc, w2c, (const __half*)nullptr,
            out, NTOK, D_MODEL, D_INNER, D_MODEL);
    }
}

// round 17
// speedup vs baseline: 2.1969x; 1.1330x over previous
#include <cuda_runtime.h>
#include <cuda_fp16.h>
#include <math.h>
#include <stdint.h>

#define D_MODEL   2048
#define D_INNER   4096
#define D_STATE   128
#define HEADDIM   64
#define NHEADS    64
#define CONV_DIM  4352     /* D_INNER + 2*D_STATE */
#define D_IN_PROJ 8512     /* 2*D_INNER + 2*D_STATE + NHEADS */
#define BATCH     2
#define TLEN      2048
#define NTOK      (BATCH*TLEN)   /* 4096 */
#define RMS_EPS   1e-5f

#define SSEG 16
#define TSEG (TLEN / SSEG)       /* 128 = SSD chunk */

// ---------------- scratch (device globals; no allocs allowed) ----------------
__device__ float g_zx [(size_t)NTOK * D_IN_PROJ];
__device__ float g_y  [(size_t)NTOK * D_INNER];

__device__ __half g_xc [(size_t)NTOK * D_MODEL];
__device__ __half g_w1c[(size_t)2 * D_IN_PROJ * D_MODEL];
__device__ __half g_yc [(size_t)NTOK * D_INNER];
__device__ __half g_w2c[(size_t)D_MODEL * D_INNER];

// fp16 scan-ready conv outputs
__device__ __half g_bh [(size_t)NTOK * D_STATE];                    // [token][n]
__device__ __half g_ch [(size_t)NTOK * D_STATE];                    // [token][n]
__device__ __half g_bt2[(size_t)BATCH * D_STATE * TLEN];            // [b][n][t]
__device__ __half g_xt [(size_t)BATCH * NHEADS * HEADDIM * TLEN];   // [b][h][p][t]

__device__ __forceinline__ uint32_t smem_to_u32(const void* p) {
    uint32_t a;
    asm("{ .reg .u64 t; cvta.to.shared.u64 t, %1; cvt.u32.u64 %0, t; }" : "=r"(a) : "l"(p));
    return a;
}
__device__ __forceinline__ void cp16(uint32_t dst, const void* src) {
    asm volatile("cp.async.cg.shared.global [%0], [%1], 16;" :: "r"(dst), "l"(src) : "memory");
}
__device__ __forceinline__ float softplus1(float raw) {
    return (raw > 20.f) ? raw : log1pf(expf(raw));
}

// ---------------- fp32 -> fp16 hi plane only ----------------
__global__ void __launch_bounds__(256) cvt_hi_kernel(
    const float* __restrict__ src, __half* __restrict__ hi, int n4)
{
    const int i = blockIdx.x * 256 + threadIdx.x;
    if (i >= n4) return;
    const float4 v = ((const float4*)src)[i];
    __half2* hp = (__half2*)(hi + (size_t)i * 4);
    hp[0] = __halves2half2(__float2half_rn(v.x), __float2half_rn(v.y));
    hp[1] = __halves2half2(__float2half_rn(v.z), __float2half_rn(v.w));
}

// ---------------- fp32 -> (hi, lo) fp16 planes ----------------
__global__ void __launch_bounds__(256) cvt_f16x2_kernel(
    const float* __restrict__ src, __half* __restrict__ hi, __half* __restrict__ lo, int n4)
{
    const int i = blockIdx.x * 256 + threadIdx.x;
    if (i >= n4) return;
    const float4 v = ((const float4*)src)[i];
    __half h0 = __float2half_rn(v.x), h1 = __float2half_rn(v.y);
    __half h2 = __float2half_rn(v.z), h3 = __float2half_rn(v.w);
    __half l0 = __float2half_rn(v.x - __half2float(h0));
    __half l1 = __float2half_rn(v.y - __half2float(h1));
    __half l2 = __float2half_rn(v.z - __half2float(h2));
    __half l3 = __float2half_rn(v.w - __half2float(h3));
    __half2* hp = (__half2*)(hi + (size_t)i * 4);
    __half2* lp = (__half2*)(lo + (size_t)i * 4);
    hp[0] = __halves2half2(h0, h1); hp[1] = __halves2half2(h2, h3);
    lp[0] = __halves2half2(l0, l1); lp[1] = __halves2half2(l2, l3);
}

// ---------------- shared MMA helpers ----------------
__device__ __forceinline__ void mma16816(float* c, const uint32_t* a, const uint32_t* b) {
    asm volatile(
        "mma.sync.aligned.m16n8k16.row.col.f32.f16.f16.f32 "
        "{%0,%1,%2,%3}, {%4,%5,%6,%7}, {%8,%9}, {%0,%1,%2,%3};"
        : "+f"(c[0]), "+f"(c[1]), "+f"(c[2]), "+f"(c[3])
        : "r"(a[0]), "r"(a[1]), "r"(a[2]), "r"(a[3]), "r"(b[0]), "r"(b[1]));
}
__device__ __forceinline__ void ldsm4(uint32_t& r0, uint32_t& r1, uint32_t& r2, uint32_t& r3,
                                      uint32_t addr) {
    asm volatile("ldmatrix.sync.aligned.m8n8.x4.shared.b16 {%0,%1,%2,%3}, [%4];"
                 : "=r"(r0), "=r"(r1), "=r"(r2), "=r"(r3) : "r"(addr));
}

// ======== fp16 GEMM template (frozen, at HW MAC ceiling) ========
#define PADH 40
#define PLANE_H (128 * PADH)
#define STAGE_B (3 * PLANE_H * 2)
#define GEMM_SMEM (3 * STAGE_B)

template<int TERMS>
__global__ void __launch_bounds__(256, 2) mma_gemm_tpl(
    const __half* __restrict__ Ahi,
    const __half* __restrict__ Bhi, const __half* __restrict__ Blo,
    float* __restrict__ C, int M, int Ncols, int K, int ldc)
{
    extern __shared__ __half sh[];
    const int tid  = threadIdx.x;
    const int wid  = tid >> 5;
    const int lane = tid & 31;
    const int g    = lane >> 2;
    const int tig  = lane & 3;
    const int bm   = blockIdx.x * 128;
    const int bn   = blockIdx.y * 128;
    const int wm   = (wid & 1) * 64;
    const int wn   = (wid >> 1) * 32;

    const uint32_t sbase = smem_to_u32(sh);

    const int a_r = lane & 15;
    const int a_c = (lane >> 4) * 8;
    const int b_r = (lane & 7) + ((lane >> 4) << 3);
    const int b_c = ((lane >> 3) & 1) * 8;

    float acc[4][4][4];
#pragma unroll
    for (int mt = 0; mt < 4; ++mt)
#pragma unroll
        for (int nt = 0; nt < 4; ++nt)
#pragma unroll
            for (int q = 0; q < 4; ++q) acc[mt][nt][q] = 0.f;

    const int NC = K >> 5;

    auto load_stage = [&](int s, int c) {
        const int kb = c * 32;
        const uint32_t stg = sbase + (uint32_t)s * STAGE_B;
#pragma unroll
        for (int i = 0; i < 2; ++i) {
            const int f   = tid + 256 * i;
            const int row = f >> 2;
            const int seg = (f & 3) * 8;
            const uint32_t doff = (uint32_t)(row * PADH + seg) * 2u;
            {
                const __half* p = Ahi + (size_t)(bm + row) * K + kb + seg;
                cp16(stg + doff, p);
            }
            {
                const int brow = bn + row;
                const int safe = (brow < Ncols) ? brow : 0;
                const uint32_t sz = (brow < Ncols) ? 16u : 0u;
                const __half* p  = Bhi + (size_t)safe * K + kb + seg;
                asm volatile("cp.async.cg.shared.global [%0], [%1], 16, %2;"
                             :: "r"(stg + (uint32_t)PLANE_H * 2u + doff), "l"(p), "r"(sz) : "memory");
                if (TERMS == 2) {
                    const __half* q2 = Blo + (size_t)safe * K + kb + seg;
                    asm volatile("cp.async.cg.shared.global [%0], [%1], 16, %2;"
                                 :: "r"(stg + (uint32_t)(2 * PLANE_H) * 2u + doff), "l"(q2), "r"(sz) : "memory");
                }
            }
        }
        asm volatile("cp.async.commit_group;" ::: "memory");
    };

    auto compute_stage = [&](int s) {
        const uint32_t stg = sbase + (uint32_t)s * STAGE_B;
        const uint32_t aHi = stg;
        const uint32_t bHi = stg + (uint32_t)PLANE_H * 2u;
        const uint32_t bLo = stg + (uint32_t)(2 * PLANE_H) * 2u;
#pragma unroll
        for (int ks = 0; ks < 2; ++ks) {
            const int k0 = ks * 16;
            uint32_t ah[4][4], bh[4][2], bl[4][2];
#pragma unroll
            for (int p = 0; p < 2; ++p) {
                const uint32_t off = (uint32_t)((wn + p * 16 + b_r) * PADH + k0 + b_c) * 2u;
                ldsm4(bh[2*p][0], bh[2*p][1], bh[2*p+1][0], bh[2*p+1][1], bHi + off);
                if (TERMS == 2)
                    ldsm4(bl[2*p][0], bl[2*p][1], bl[2*p+1][0], bl[2*p+1][1], bLo + off);
            }
#pragma unroll
            for (int mt = 0; mt < 4; ++mt) {
                const uint32_t off = (uint32_t)((wm + mt * 16 + a_r) * PADH + k0 + a_c) * 2u;
                ldsm4(ah[mt][0], ah[mt][1], ah[mt][2], ah[mt][3], aHi + off);
            }
#pragma unroll
            for (int mt = 0; mt < 4; ++mt)
#pragma unroll
                for (int nt = 0; nt < 4; ++nt)
                    mma16816(acc[mt][nt], ah[mt], bh[nt]);
            if (TERMS == 2) {
#pragma unroll
                for (int mt = 0; mt < 4; ++mt)
#pragma unroll
                    for (int nt = 0; nt < 4; ++nt)
                        mma16816(acc[mt][nt], ah[mt], bl[nt]);
            }
        }
    };

    load_stage(0, 0);
    load_stage(1, 1);
    for (int c = 0; c < NC; ++c) {
        if (c + 2 < NC) {
            asm volatile("cp.async.wait_group 1;" ::: "memory");
        } else {
            asm volatile("cp.async.wait_group 0;" ::: "memory");
        }
        __syncthreads();
        if (c + 2 < NC) load_stage((c + 2) % 3, c + 2);
        compute_stage(c % 3);
    }

#pragma unroll
    for (int mt = 0; mt < 4; ++mt) {
        const int row0 = bm + wm + mt * 16 + g;
#pragma unroll
        for (int nt = 0; nt < 4; ++nt) {
            const int col = bn + wn + nt * 8 + tig * 2;
            if (col < Ncols) {
                *(float2*)(C + (size_t)row0 * ldc + col)       = make_float2(acc[mt][nt][0], acc[mt][nt][1]);
                *(float2*)(C + (size_t)(row0 + 8) * ldc + col) = make_float2(acc[mt][nt][2], acc[mt][nt][3]);
            }
        }
    }
}

// ---------------- conv+SiLU for x channels: emits transposed fp16 g_xt ----------------
__global__ void __launch_bounds__(256) conv_x_kernel(
    const float* __restrict__ cw, const float* __restrict__ cb)
{
    __shared__ __half tile[64][136];
    const int h  = blockIdx.x;
    const int tb = blockIdx.y * 128;
    const int b  = blockIdx.z;
    const int tid = threadIdx.x;
    const int p  = tid >> 2;
    const int tg = tid & 3;
    const int c  = h * HEADDIM + p;

    const float w0 = cw[c*4+0], w1 = cw[c*4+1], w2 = cw[c*4+2], w3 = cw[c*4+3];
    const float bias = cb[c];

    const float* base = g_zx + ((size_t)b * TLEN) * D_IN_PROJ + D_INNER + c;
    const int ts = tb + tg * 32;

    float x0 = (ts >= 3) ? base[(size_t)(ts-3) * D_IN_PROJ] : 0.f;
    float x1 = (ts >= 2) ? base[(size_t)(ts-2) * D_IN_PROJ] : 0.f;
    float x2 = (ts >= 1) ? base[(size_t)(ts-1) * D_IN_PROJ] : 0.f;

#pragma unroll 4
    for (int i = 0; i < 32; ++i) {
        const int t = ts + i;
        const float x3 = base[(size_t)t * D_IN_PROJ];
        const float v  = bias + x0*w0 + x1*w1 + x2*w2 + x3*w3;
        tile[p][tg * 32 + i] = __float2half_rn(v / (1.f + expf(-v)));
        x0 = x1; x1 = x2; x2 = x3;
    }
    __syncthreads();

    const int p2 = tid >> 2;
    const int sg = (tid & 3) * 32;
    __half* dst = g_xt + ((size_t)((b * NHEADS + h) * HEADDIM) + p2) * TLEN + tb + sg;
#pragma unroll
    for (int k = 0; k < 4; ++k)
        *(uint4*)(dst + k * 8) = *(const uint4*)(&tile[p2][sg + k * 8]);
}

// ---------------- conv+SiLU for B/C channels: emits g_bh, g_ch, g_bt2 ----------------
__global__ void __launch_bounds__(256) conv_bc_kernel(
    const float* __restrict__ cw, const float* __restrict__ cb)
{
    const int tid = threadIdx.x;
    const int c   = D_INNER + tid;
    const int b   = blockIdx.z;
    const int t0  = blockIdx.y * 32;
    const bool isB = (tid < 128);
    const int n   = isB ? tid : (tid - 128);

    const float w0 = cw[c*4+0], w1 = cw[c*4+1], w2 = cw[c*4+2], w3 = cw[c*4+3];
    const float bias = cb[c];

    const float* base = g_zx + ((size_t)b * TLEN) * D_IN_PROJ + D_INNER + c;

    float x0 = (t0 >= 3) ? base[(size_t)(t0-3) * D_IN_PROJ] : 0.f;
    float x1 = (t0 >= 2) ? base[(size_t)(t0-2) * D_IN_PROJ] : 0.f;
    float x2 = (t0 >= 1) ? base[(size_t)(t0-1) * D_IN_PROJ] : 0.f;

    __half* bh  = g_bh  + ((size_t)b * TLEN) * D_STATE + n;
    __half* ch  = g_ch  + ((size_t)b * TLEN) * D_STATE + n;
    __half* bt2 = g_bt2 + ((size_t)(b * D_STATE + n)) * TLEN;

#pragma unroll 4
    for (int t = t0; t < t0 + 32; ++t) {
        const float x3 = base[(size_t)t * D_IN_PROJ];
        const float v  = bias + x0*w0 + x1*w1 + x2*w2 + x3*w3;
        const __half hv = __float2half_rn(v / (1.f + expf(-v)));
        if (isB) {
            bh[(size_t)t * D_STATE] = hv;
            bt2[t] = hv;
        } else {
            ch[(size_t)t * D_STATE] = hv;
        }
        x0 = x1; x1 = x2; x2 = x3;
    }
}

// ======================= fully-fused SSD scan, fp16 cp.async staging =======================
#define PADN 136
#define PADNF 132
#define OFF_CT  0
#define OFF_BT  17408
#define OFF_BT2 34816
#define OFF_L   52224
#define OFF_XT  69632
#define OFF_SPH 78336
#define SSD_FLT 87040
#define SSD_SMEM (SSD_FLT * 2 + (8448 + 388 + 4 + 64) * 4)

__global__ void __launch_bounds__(256, 1) ssd_fused_kernel(
    const float* __restrict__ dt_bias, const float* __restrict__ A_log,
    const float* __restrict__ Dskip)
{
    extern __shared__ __half sh[];
    float* fb   = (float*)(sh + SSD_FLT);
    float* Sf   = fb;
    float* sdt  = fb + 8448;
    float* sda  = sdt + 128;
    float* scum = sda + 128;
    float* fw   = scum + 128;
    __half* sWjh = (__half*)(fw + 4);          // [128]

    const int h = blockIdx.x, b = blockIdx.y;
    const int tid = threadIdx.x;
    const int wid = tid >> 5;
    const int lane = tid & 31;
    const int g   = lane >> 2;
    const int tig = lane & 3;
    const int a_r = lane & 15;
    const int a_c = (lane >> 4) * 8;
    const int b_r = (lane & 7) + ((lane >> 4) << 3);
    const int b_c = ((lane >> 3) & 1) * 8;

    const float Acoef = -expf(A_log[h]);
    const float dtb   = dt_bias[h];
    const float dsk   = Dskip[h];

    const uint32_t sb   = smem_to_u32(sh);
    const uint32_t uCT  = sb + OFF_CT  * 2u;
    const uint32_t uBT  = sb + OFF_BT  * 2u;
    const uint32_t uBT2 = sb + OFF_BT2 * 2u;
    const uint32_t uXT  = sb + OFF_XT  * 2u;
    const uint32_t uSPH = sb + OFF_SPH * 2u;

    const __half* bh_b  = g_bh  + (size_t)b * TLEN * D_STATE;
    const __half* ch_b  = g_ch  + (size_t)b * TLEN * D_STATE;
    const __half* bt2_b = g_bt2 + (size_t)b * D_STATE * TLEN;
    const __half* xt_b  = g_xt  + (size_t)(b * NHEADS + h) * HEADDIM * TLEN;

    for (int e = tid; e < 64 * PADNF; e += 256) Sf[e] = 0.f;
    __syncthreads();

    for (int s = 0; s < SSEG; ++s) {
        const int t0 = s * TSEG;
        const size_t rbase = (size_t)(b * TLEN + t0);

        // ---- phase 1: async staging of CT, BT, BT2(raw), XT ----
#pragma unroll
        for (int i = 0; i < 28; ++i) {
            const int flat = tid + 256 * i;
            if (flat < 2048) {
                const int row = flat >> 4, seg = (flat & 15) * 8;
                cp16(uBT + (uint32_t)(row * PADN + seg) * 2u,
                     bh_b + (size_t)(t0 + row) * D_STATE + seg);
            } else if (flat < 4096) {
                const int f = flat - 2048, row = f >> 4, seg = (f & 15) * 8;
                cp16(uCT + (uint32_t)(row * PADN + seg) * 2u,
                     ch_b + (size_t)(t0 + row) * D_STATE + seg);
            } else if (flat < 6144) {
                const int f = flat - 4096, row = f >> 4, seg = (f & 15) * 8;
                cp16(uBT2 + (uint32_t)(row * PADN + seg) * 2u,
                     bt2_b + (size_t)row * TLEN + t0 + seg);
            } else {
                const int f = flat - 6144, row = f >> 4, seg = (f & 15) * 8;
                cp16(uXT + (uint32_t)(row * PADN + seg) * 2u,
                     xt_b + (size_t)row * TLEN + t0 + seg);
            }
        }
        asm volatile("cp.async.commit_group;" ::: "memory");

        // ---- phase 2: dt, dA, warp-level prefix scan ----
        float vscan = 0.f;
        if (tid < 128) {
            const float raw = g_zx[(rbase + tid) * D_IN_PROJ + (D_INNER + CONV_DIM) + h] + dtb;
            const float dt  = softplus1(raw);
            sdt[tid] = dt;
            sda[tid] = expf(dt * Acoef);
            float v = dt;
#pragma unroll
            for (int o = 1; o < 32; o <<= 1) {
                const float t = __shfl_up_sync(0xffffffffu, v, o);
                if (lane >= o) v += t;
            }
            vscan = v;
            if (lane == 31) fw[wid] = v;
        }
        __syncthreads();
        if (tid < 128) {
            float off = 0.f;
            for (int w = 0; w < wid; ++w) off += fw[w];
            scum[tid] = off + vscan;
        }
        __syncthreads();

        const float cumTot = scum[127];
        const float P = expf(Acoef * cumTot);

        // ---- phase 3: wj + L build (overlaps in-flight cp.async) ----
        if (tid < 128) {
            const int j = tid;
            sWjh[j] = __float2half_rn(sdt[j] * expf(Acoef * (cumTot - scum[j])));
            const float dtj = sdt[j];
            float val = 0.f;
            for (int i = 0; i < 128; ++i) {
                val = (i == j) ? dtj : sda[i] * val;
                sh[OFF_L + i * PADN + j] = __float2half_rn(val);
            }
        }
        asm volatile("cp.async.wait_group 0;" ::: "memory");
        __syncthreads();

        // ---- phase 4: BT2 *= wj (half2), SPH = fp16(Sf) ----
#pragma unroll
        for (int i = 0; i < 32; ++i) {
            const int idx = tid + 256 * i;
            const int n = idx >> 6, q = idx & 63;
            __half2* pp = (__half2*)(sh + OFF_BT2 + n * PADN + 2 * q);
            *pp = __hmul2(*pp, *(const __half2*)(sWjh + 2 * q));
        }
        if (s > 0) {
            for (int e = tid; e < 64 * 128; e += 256) {
                const int p = e >> 7, n = e & 127;
                sh[OFF_SPH + p * PADN + n] = __float2half_rn(Sf[p * PADNF + n]);
            }
        }
        __syncthreads();

        const int wm1 = wid * 16;
        const int i0  = wm1 + g;

        // ---- Gcorr = C @ Sprev^T ----
        float accc[8][4];
#pragma unroll
        for (int nt = 0; nt < 8; ++nt)
#pragma unroll
            for (int q = 0; q < 4; ++q) accc[nt][q] = 0.f;
        if (s > 0) {
#pragma unroll
            for (int ks = 0; ks < 8; ++ks) {
                const int k0 = ks * 16;
                uint32_t ah[4];
                ldsm4(ah[0], ah[1], ah[2], ah[3],
                      uCT + (uint32_t)((wm1 + a_r) * PADN + k0 + a_c) * 2u);
                uint32_t bhf[8][2];
#pragma unroll
                for (int p4 = 0; p4 < 4; ++p4)
                    ldsm4(bhf[2*p4][0], bhf[2*p4][1], bhf[2*p4+1][0], bhf[2*p4+1][1],
                          uSPH + (uint32_t)((p4 * 16 + b_r) * PADN + k0 + b_c) * 2u);
#pragma unroll
                for (int nt = 0; nt < 8; ++nt)
                    mma16816(accc[nt], ah, bhf[nt]);
            }
        }

        // ---- G = C @ B^T ----
        float acc1[16][4];
#pragma unroll
        for (int nt = 0; nt < 16; ++nt)
#pragma unroll
            for (int q = 0; q < 4; ++q) acc1[nt][q] = 0.f;
#pragma unroll
        for (int ks = 0; ks < 8; ++ks) {
            const int k0 = ks * 16;
            uint32_t ah[4];
            ldsm4(ah[0], ah[1], ah[2], ah[3],
                  uCT + (uint32_t)((wm1 + a_r) * PADN + k0 + a_c) * 2u);
            uint32_t bhf[16][2];
#pragma unroll
            for (int p4 = 0; p4 < 8; ++p4)
                ldsm4(bhf[2*p4][0], bhf[2*p4][1], bhf[2*p4+1][0], bhf[2*p4+1][1],
                      uBT + (uint32_t)((p4 * 16 + b_r) * PADN + k0 + b_c) * 2u);
#pragma unroll
            for (int nt = 0; nt < 16; ++nt)
                mma16816(acc1[nt], ah, bhf[nt]);
        }

        // ---- apply L, overwrite warp-private CT rows with Gp ----
#pragma unroll
        for (int nt = 0; nt < 16; ++nt) {
            const int col = nt * 8 + tig * 2;
            const float2 f0 = __half22float2(*(__half2*)(sh + OFF_L + i0 * PADN + col));
            const float2 f1 = __half22float2(*(__half2*)(sh + OFF_L + (i0 + 8) * PADN + col));
            *(__half2*)(sh + OFF_CT + i0 * PADN + col)       = __floats2half2_rn(acc1[nt][0] * f0.x, acc1[nt][1] * f0.y);
            *(__half2*)(sh + OFF_CT + (i0 + 8) * PADN + col) = __floats2half2_rn(acc1[nt][2] * f1.x, acc1[nt][3] * f1.y);
        }
        __syncwarp();

        // ---- Y_intra = Gp @ X^T ----
        float acc2[8][4];
#pragma unroll
        for (int nt = 0; nt < 8; ++nt)
#pragma unroll
            for (int q = 0; q < 4; ++q) acc2[nt][q] = 0.f;
#pragma unroll
        for (int ks = 0; ks < 8; ++ks) {
            const int k0 = ks * 16;
            uint32_t ah[4];
            ldsm4(ah[0], ah[1], ah[2], ah[3],
                  uCT + (uint32_t)((wm1 + a_r) * PADN + k0 + a_c) * 2u);
            uint32_t bhf[8][2];
#pragma unroll
            for (int p4 = 0; p4 < 4; ++p4)
                ldsm4(bhf[2*p4][0], bhf[2*p4][1], bhf[2*p4+1][0], bhf[2*p4+1][1],
                      uXT + (uint32_t)((p4 * 16 + b_r) * PADN + k0 + b_c) * 2u);
#pragma unroll
            for (int nt = 0; nt < 8; ++nt)
                mma16816(acc2[nt], ah, bhf[nt]);
        }

        // ---- Y epilogue: + ri*Gcorr + Dskip*x (x from smem XT) ----
        {
            const float ri0 = expf(Acoef * scum[i0]);
            const float ri1 = expf(Acoef * scum[i0 + 8]);
            const size_t r0 = rbase + i0;
            const size_t r1 = r0 + 8;
#pragma unroll
            for (int nt = 0; nt < 8; ++nt) {
                const int col = nt * 8 + tig * 2;
                const float x00 = __half2float(sh[OFF_XT + col * PADN + i0]);
                const float x01 = __half2float(sh[OFF_XT + (col + 1) * PADN + i0]);
                const float x10 = __half2float(sh[OFF_XT + col * PADN + i0 + 8]);
                const float x11 = __half2float(sh[OFF_XT + (col + 1) * PADN + i0 + 8]);
                *(float2*)(g_y + r0 * D_INNER + h * HEADDIM + col) =
                    make_float2(acc2[nt][0] + ri0 * accc[nt][0] + dsk * x00,
                                acc2[nt][1] + ri0 * accc[nt][1] + dsk * x01);
                *(float2*)(g_y + r1 * D_INNER + h * HEADDIM + col) =
                    make_float2(acc2[nt][2] + ri1 * accc[nt][2] + dsk * x10,
                                acc2[nt][3] + ri1 * accc[nt][3] + dsk * x11);
            }
        }

        // ---- Snew^T = X @ (wj-scaled B)^T ----
        const int wm3 = (wid & 3) * 16;
        const int nb3 = (wid >> 2) * 64;
        float acc3[8][4];
#pragma unroll
        for (int nt = 0; nt < 8; ++nt)
#pragma unroll
            for (int q = 0; q < 4; ++q) acc3[nt][q] = 0.f;
#pragma unroll
        for (int ks = 0; ks < 8; ++ks) {
            const int k0 = ks * 16;
            uint32_t ah[4];
            ldsm4(ah[0], ah[1], ah[2], ah[3],
                  uXT + (uint32_t)((wm3 + a_r) * PADN + k0 + a_c) * 2u);
            uint32_t bhf[8][2];
#pragma unroll
            for (int p4 = 0; p4 < 4; ++p4)
                ldsm4(bhf[2*p4][0], bhf[2*p4][1], bhf[2*p4+1][0], bhf[2*p4+1][1],
                      uBT2 + (uint32_t)((nb3 + p4 * 16 + b_r) * PADN + k0 + b_c) * 2u);
#pragma unroll
            for (int nt = 0; nt < 8; ++nt)
                mma16816(acc3[nt], ah, bhf[nt]);
        }
        {
            const int p0 = wm3 + g;
#pragma unroll
            for (int nt = 0; nt < 8; ++nt) {
                const int n = nb3 + nt * 8 + tig * 2;
                float* s0 = Sf + p0 * PADNF + n;
                float* s1 = Sf + (p0 + 8) * PADNF + n;
                s0[0] = P * s0[0] + acc3[nt][0];
                s0[1] = P * s0[1] + acc3[nt][1];
                s1[0] = P * s1[0] + acc3[nt][2];
                s1[1] = P * s1[1] + acc3[nt][3];
            }
        }
        __syncthreads();
    }
}

// ---------------- gate + RMSNorm, emits fp16 hi plane directly ----------------
__global__ void __launch_bounds__(256) gate_norm_cvt_kernel(
    const float* __restrict__ nw, __half* __restrict__ yhi)
{
    const int row = blockIdx.x;
    const int tid = threadIdx.x;
    const float* zrow = g_zx + (size_t)row * D_IN_PROJ;
    const float* yrow = g_y  + (size_t)row * D_INNER;

    float g[16];
    float ss = 0.f;
#pragma unroll
    for (int i = 0; i < 4; ++i) {
        const int e = i * 1024 + tid * 4;
        const float4 yv = *(const float4*)(yrow + e);
        const float4 zv = *(const float4*)(zrow + e);
        float g0 = yv.x * (zv.x / (1.f + expf(-zv.x)));
        float g1 = yv.y * (zv.y / (1.f + expf(-zv.y)));
        float g2 = yv.z * (zv.z / (1.f + expf(-zv.z)));
        float g3 = yv.w * (zv.w / (1.f + expf(-zv.w)));
        g[i*4+0] = g0; g[i*4+1] = g1; g[i*4+2] = g2; g[i*4+3] = g3;
        ss += g0*g0 + g1*g1 + g2*g2 + g3*g3;
    }

    ss += __shfl_xor_sync(0xffffffffu, ss, 16);
    ss += __shfl_xor_sync(0xffffffffu, ss, 8);
    ss += __shfl_xor_sync(0xffffffffu, ss, 4);
    ss += __shfl_xor_sync(0xffffffffu, ss, 2);
    ss += __shfl_xor_sync(0xffffffffu, ss, 1);
    __shared__ float red[8];
    if ((tid & 31) == 0) red[tid >> 5] = ss;
    __syncthreads();
    float tot = 0.f;
#pragma unroll
    for (int w = 0; w < 8; ++w) tot += red[w];

    const float scale = rsqrtf(tot / (float)D_INNER + RMS_EPS);
#pragma unroll
    for (int i = 0; i < 4; ++i) {
        const int e = i * 1024 + tid * 4;
        const float v0 = g[i*4+0] * scale * nw[e+0];
        const float v1 = g[i*4+1] * scale * nw[e+1];
        const float v2 = g[i*4+2] * scale * nw[e+2];
        const float v3 = g[i*4+3] * scale * nw[e+3];
        __half2* hp = (__half2*)(yhi + (size_t)row * D_INNER + e);
        hp[0] = __halves2half2(__float2half_rn(v0), __float2half_rn(v1));
        hp[1] = __halves2half2(__float2half_rn(v2), __float2half_rn(v3));
    }
}

// ---------------- launch ----------------
extern "C" void kernel_launch(void* const* d_in, const int* in_sizes, int n_in,
                              void* d_out, int out_size)
{
    const float* x          = (const float*)d_in[0];
    const float* in_proj_w  = (const float*)d_in[3];
    const float* conv_w     = (const float*)d_in[4];
    const float* conv_b     = (const float*)d_in[5];
    const float* dt_bias    = (const float*)d_in[6];
    const float* A_log      = (const float*)d_in[7];
    const float* Dskip      = (const float*)d_in[8];
    const float* norm_w     = (const float*)d_in[9];
    const float* out_proj_w = (const float*)d_in[10];
    float* out = (float*)d_out;

    float *zx;
    __half *xc, *w1c, *yc, *w2c;
    cudaGetSymbolAddress((void**)&zx,  g_zx);
    cudaGetSymbolAddress((void**)&xc,  g_xc);
    cudaGetSymbolAddress((void**)&w1c, g_w1c);
    cudaGetSymbolAddress((void**)&yc,  g_yc);
    cudaGetSymbolAddress((void**)&w2c, g_w2c);

    cudaFuncSetAttribute(mma_gemm_tpl<1>,
                         cudaFuncAttributeMaxDynamicSharedMemorySize, GEMM_SMEM);
    cudaFuncSetAttribute(mma_gemm_tpl<2>,
                         cudaFuncAttributeMaxDynamicSharedMemorySize, GEMM_SMEM);
    cudaFuncSetAttribute(ssd_fused_kernel,
                         cudaFuncAttributeMaxDynamicSharedMemorySize, SSD_SMEM);

    const int c0 = D_INNER + CONV_DIM;          // 8448
    __half* w1lo = w1c + (size_t)D_IN_PROJ * D_MODEL;   // mutable: written by cvt

    // 0) conversions: x hi; w1 hi [0,8448) + hi/lo dt slice; w2 hi
    {
        const int nx = NTOK * D_MODEL / 4;
        cvt_hi_kernel<<<(nx + 255) / 256, 256>>>(x, xc, nx);
        const int nw1a = c0 * D_MODEL / 4;
        cvt_hi_kernel<<<(nw1a + 255) / 256, 256>>>(in_proj_w, w1c, nw1a);
        const int nw1b = (D_IN_PROJ - c0) * D_MODEL / 4;   // 64 rows
        cvt_f16x2_kernel<<<(nw1b + 255) / 256, 256>>>(
            in_proj_w + (size_t)c0 * D_MODEL,
            w1c  + (size_t)c0 * D_MODEL,
            w1lo + (size_t)c0 * D_MODEL, nw1b);
        const int nw2 = D_MODEL * D_INNER / 4;
        cvt_hi_kernel<<<(nw2 + 255) / 256, 256>>>(out_proj_w, w2c, nw2);
    }

    // 1a) in_proj cols [0, 8448): single-term
    {
        dim3 grid(NTOK / 128, c0 / 128);
        mma_gemm_tpl<1><<<grid, 256, GEMM_SMEM>>>(
            xc, w1c, (const __half*)nullptr,
            zx, NTOK, c0, D_MODEL, D_IN_PROJ);
    }
    // 1b) dt cols: two-term
    {
        dim3 grid(NTOK / 128, 1);
        mma_gemm_tpl<2><<<grid, 256, GEMM_SMEM>>>(
            xc,
            w1c  + (size_t)c0 * D_MODEL,
            (const __half*)(w1lo + (size_t)c0 * D_MODEL),
            zx + c0, NTOK, D_IN_PROJ - c0, D_MODEL, D_IN_PROJ);
    }
    // 2) conv + silu -> fp16 scan-ready tensors
    {
        dim3 gx(NHEADS, TLEN / 128, BATCH);
        conv_x_kernel<<<gx, 256>>>(conv_w, conv_b);
        dim3 gbc(1, TLEN / 32, BATCH);
        conv_bc_kernel<<<gbc, 256>>>(conv_w, conv_b);
    }
    // 3) fused SSD scan
    {
        dim3 grid(NHEADS, BATCH);
        ssd_fused_kernel<<<grid, 256, SSD_SMEM>>>(dt_bias, A_log, Dskip);
    }
    // 4) gate + RMSNorm + fp16
    gate_norm_cvt_kernel<<<NTOK, 256>>>(norm_w, yc);

    // 5) out_proj: single-term
    {
        dim3 grid(NTOK / 128, D_MODEL / 128);
        mma_gemm_tpl<1><<<grid, 256, GEMM_SMEM>>>(
            yc, w2c, (const __half*)nullptr,
            out, NTOK, D_MODEL, D_INNER, D_MODEL);
    }
}